// round 2
// baseline (speedup 1.0000x reference)
#include <cuda_runtime.h>
#include <math.h>

#define BTn 512
#define En  512
#define Hn  1024
#define Gn  4096
#define NCn 33
#define VBn 32
#define NSTEPS 128

// ---- scratch (device globals; no allocation allowed) ----
__device__ __align__(256) float d_cond[BTn*Hn];
__device__ __align__(256) float d_condG0[BTn*Gn];
__device__ __align__(256) float d_bvecM[3*Gn];   // [0,G): bvec  [G,2G): M2 row0  [2G,3G): M2 row1
__device__ __align__(256) float d_g0[BTn*Gn];
__device__ __align__(256) float d_g1[BTn*Gn];
__device__ __align__(256) float d_h0[BTn*Hn];
__device__ __align__(256) float d_c0[BTn*Hn];
__device__ __align__(256) float d_h1[BTn*Hn];
__device__ __align__(256) float d_c1[BTn*Hn];
__device__ __align__(256) float d_cur[BTn*2];

__device__ __forceinline__ float* bufById(int id){
  switch(id){
    case 0: return d_cond;   case 1: return d_condG0;
    case 2: return d_g0;     case 3: return d_g1;
    case 4: return d_h0;     case 5: return d_h1;
    case 6: return d_c0;     case 7: return d_c1;
    default: return nullptr;
  }
}

// ---- init: zero states, broadcast sos into cur ----
__global__ void k_init(const float* __restrict__ sos){
  int idx = blockIdx.x*blockDim.x + threadIdx.x;
  if (idx < BTn*Hn){
    d_h0[idx]=0.f; d_c0[idx]=0.f; d_h1[idx]=0.f; d_c1[idx]=0.f;
  }
  if (idx < BTn){
    d_cur[idx*2+0] = sos[0];
    d_cur[idx*2+1] = sos[1];
  }
}

// ---- precompute bvec = bi@Wih0_top + bih0 + bhh0 ; M2 = Wi@Wih0_top ----
__global__ void k_prep(const float* __restrict__ Wih0, const float* __restrict__ bi,
                       const float* __restrict__ Wi,   const float* __restrict__ bih0,
                       const float* __restrict__ bhh0){
  int j = blockIdx.x*blockDim.x + threadIdx.x;   // 0..4095
  float ab=0.f, a0=0.f, a1=0.f;
  for (int k=0;k<Hn;k++){
    float w = Wih0[(size_t)k*Gn + j];
    ab = fmaf(bi[k],     w, ab);
    a0 = fmaf(Wi[k],     w, a0);
    a1 = fmaf(Wi[Hn+k],  w, a1);
  }
  d_bvecM[j]        = bih0[j] + bhh0[j] + ab;
  d_bvecM[Gn+j]     = a0;
  d_bvecM[2*Gn+j]   = a1;
}

// ---- generic 128x128x16 tiled fp32 GEMM, 256 threads, 8x8 per thread ----
#define AS_LD 132
template<int HAS2,int PRE,int CURM>
__global__ __launch_bounds__(256) void gemm128(
    const float* __restrict__ Aext,
    const float* __restrict__ W,       const float* __restrict__ W2,
    const float* __restrict__ biasExt, const float* __restrict__ biasExt2,
    int idA, int idA2, int useBvecBias, int idC, int N, int K)
{
  __shared__ float As[16*AS_LD];
  __shared__ float Ws[16*AS_LD];
  const int m0 = blockIdx.y*128, n0 = blockIdx.x*128;
  const int tid  = threadIdx.x;
  const int trow = tid>>4, tcol = tid&15;

  float acc[8][8];
  #pragma unroll
  for(int i=0;i<8;i++)
    #pragma unroll
    for(int j=0;j<8;j++) acc[i][j]=0.f;

  const float* A0 = Aext ? Aext : bufById(idA);

  #pragma unroll
  for (int src=0; src < (HAS2?2:1); ++src){
    const float* Ap = src ? bufById(idA2) : A0;
    const float* Wp = src ? W2 : W;
    for (int k0=0;k0<K;k0+=16){
      // load A tile [128 x 16] (transposed into As[k][m])
      #pragma unroll
      for (int i=0;i<2;i++){
        int f = tid + i*256;
        int r = f>>2, c = f&3;
        float4 v = *(const float4*)(Ap + (size_t)(m0+r)*K + k0 + c*4);
        As[(c*4+0)*AS_LD + r]=v.x;
        As[(c*4+1)*AS_LD + r]=v.y;
        As[(c*4+2)*AS_LD + r]=v.z;
        As[(c*4+3)*AS_LD + r]=v.w;
      }
      // load W tile [16 x 128]
      #pragma unroll
      for (int i=0;i<2;i++){
        int f = tid + i*256;
        int kr = f>>5, nc = f&31;
        float4 v = *(const float4*)(Wp + (size_t)(k0+kr)*N + n0 + nc*4);
        *(float4*)(&Ws[kr*AS_LD + nc*4]) = v;
      }
      __syncthreads();
      #pragma unroll
      for (int kk=0;kk<16;kk++){
        float a[8], b[8];
        *(float4*)(a)   = *(const float4*)(&As[kk*AS_LD + trow*8]);
        *(float4*)(a+4) = *(const float4*)(&As[kk*AS_LD + trow*8+4]);
        *(float4*)(b)   = *(const float4*)(&Ws[kk*AS_LD + tcol*8]);
        *(float4*)(b+4) = *(const float4*)(&Ws[kk*AS_LD + tcol*8+4]);
        #pragma unroll
        for(int i=0;i<8;i++)
          #pragma unroll
          for(int j=0;j<8;j++)
            acc[i][j] = fmaf(a[i], b[j], acc[i][j]);
      }
      __syncthreads();
    }
  }

  float* C = bufById(idC);
  #pragma unroll
  for (int i=0;i<8;i++){
    int r = m0 + trow*8 + i;
    float cu0=0.f, cu1=0.f;
    if (CURM){ cu0 = d_cur[r*2]; cu1 = d_cur[r*2+1]; }
    #pragma unroll
    for (int j=0;j<8;j++){
      int col = n0 + tcol*8 + j;
      float v = acc[i][j];
      if (PRE)         v += d_condG0[(size_t)r*Gn + col];
      if (CURM)        v += cu0*d_bvecM[Gn+col] + cu1*d_bvecM[2*Gn+col];
      if (biasExt)     v += biasExt[col];
      if (biasExt2)    v += biasExt2[col];
      if (useBvecBias) v += d_bvecM[col];
      C[(size_t)r*N + col] = v;
    }
  }
}

// ---- LSTM cell elementwise update (gate order i,f,g,o) ----
__global__ void lstm_cell(int idG, int idH, int idCst){
  int idx = blockIdx.x*blockDim.x + threadIdx.x;   // BT*H
  const float* g = bufById(idG);
  float* h = bufById(idH);
  float* c = bufById(idCst);
  int r = idx >> 10, j = idx & 1023;
  const float* gr = g + (size_t)r*Gn;
  float gi = gr[j], gf = gr[Hn+j], gg = gr[2*Hn+j], go = gr[3*Hn+j];
  float iv = 1.f/(1.f+expf(-gi));
  float fv = 1.f/(1.f+expf(-gf));
  float gv = tanhf(gg);
  float ov = 1.f/(1.f+expf(-go));
  float cn = fv*c[idx] + iv*gv;
  c[idx] = cn;
  h[idx] = ov*tanhf(cn);
}

// ---- output projection + argmax/sigmoid feedback; one block per row ----
__global__ __launch_bounds__(128) void k_logit(const float* __restrict__ Wo,
      const float* __restrict__ bo, float* __restrict__ out, int s){
  __shared__ float red[128*NCn];
  __shared__ float lg[NCn];
  int r = blockIdx.x;
  const float* hr = d_h1 + (size_t)r*Hn;
  float acc[NCn];
  #pragma unroll
  for(int c=0;c<NCn;c++) acc[c]=0.f;
  for (int k=threadIdx.x; k<Hn; k+=128){
    float a = hr[k];
    const float* w = Wo + (size_t)k*NCn;
    #pragma unroll
    for(int c=0;c<NCn;c++) acc[c] = fmaf(a, w[c], acc[c]);
  }
  #pragma unroll
  for(int c=0;c<NCn;c++) red[threadIdx.x*NCn + c] = acc[c];
  __syncthreads();
  if (threadIdx.x < NCn){
    float sv = bo[threadIdx.x];
    for (int t=0;t<128;t++) sv += red[t*NCn + threadIdx.x];
    int b = r>>6, tt = r&63;
    out[ (((size_t)b*NCn + threadIdx.x)*64 + tt)*128 + s ] = sv;
    lg[threadIdx.x] = sv;
  }
  __syncthreads();
  if (threadIdx.x==0){
    d_cur[r*2] = (lg[0] > 0.f) ? 1.f : 0.f;        // sigmoid(l)>0.5  <=>  l>0
    float best = lg[1]; int bidx = 0;               // first-max == jnp.argmax
    #pragma unroll
    for (int c=2;c<NCn;c++){ if (lg[c] > best){ best=lg[c]; bidx=c-1; } }
    d_cur[r*2+1] = (float)bidx * (1.f/(VBn-1));
  }
}

extern "C" void kernel_launch(void* const* d_in, const int* in_sizes, int n_in,
                              void* d_out, int out_size){
  const float* x    = (const float*)d_in[0];
  const float* sos  = (const float*)d_in[1];
  const float* Wc   = (const float*)d_in[2];
  const float* bc   = (const float*)d_in[3];
  const float* Wi   = (const float*)d_in[4];
  const float* bi   = (const float*)d_in[5];
  const float* Wih0 = (const float*)d_in[6];
  const float* Whh0 = (const float*)d_in[7];
  const float* bih0 = (const float*)d_in[8];
  const float* bhh0 = (const float*)d_in[9];
  const float* Wih1 = (const float*)d_in[10];
  const float* Whh1 = (const float*)d_in[11];
  const float* bih1 = (const float*)d_in[12];
  const float* bhh1 = (const float*)d_in[13];
  const float* Wo   = (const float*)d_in[14];
  const float* bo   = (const float*)d_in[15];
  float* out = (float*)d_out;

  // state init + step-invariant precompute (inside the graph; deterministic per replay)
  k_init<<<(BTn*Hn+255)/256, 256>>>(sos);
  k_prep<<<Gn/128, 128>>>(Wih0, bi, Wi, bih0, bhh0);

  // cond = x@Wc + bc        [512,1024], K=512
  gemm128<0,0,0><<<dim3(Hn/128, BTn/128), 256>>>(x, Wc, nullptr, bc, nullptr,
        -1, -1, 0, /*idC=*/0, Hn, En);
  // condG0 = cond@Wih0_bot + bvec     [512,4096], K=1024
  gemm128<0,0,0><<<dim3(Gn/128, BTn/128), 256>>>(nullptr, Wih0 + (size_t)Hn*Gn, nullptr,
        nullptr, nullptr, /*idA=*/0, -1, /*useBvecBias=*/1, /*idC=*/1, Gn, Hn);

  for (int s=0;s<NSTEPS;s++){
    // g0 = h0@Whh0 + condG0 + cur@M2
    gemm128<0,1,1><<<dim3(Gn/128, BTn/128), 256>>>(nullptr, Whh0, nullptr, nullptr, nullptr,
        /*idA=*/4, -1, 0, /*idC=*/2, Gn, Hn);
    lstm_cell<<<BTn*Hn/256,256>>>(2, 4, 6);
    // g1 = h0@Wih1 + h1@Whh1 + bih1 + bhh1
    gemm128<1,0,0><<<dim3(Gn/128, BTn/128), 256>>>(nullptr, Wih1, Whh1, bih1, bhh1,
        /*idA=*/4, /*idA2=*/5, 0, /*idC=*/3, Gn, Hn);
    lstm_cell<<<BTn*Hn/256,256>>>(3, 5, 7);
    // logits -> out, and feedback cur = [note>0, argmax/31]
    k_logit<<<BTn,128>>>(Wo, bo, out, s);
  }
}

// round 5
// speedup vs baseline: 3.7054x; 3.7054x over previous
#include <cuda_runtime.h>
#include <cuda_fp16.h>
#include <math.h>
#include <stdint.h>

#define BTn 512
#define En  512
#define Hn  1024
#define Gn  4096
#define NCn 33
#define VBn 32
#define NSTEPS 128
#define KC 64

// ============================ device globals ============================
__device__ __align__(256) float d_cond[BTn*Hn];
__device__ __align__(256) float d_condG0p[BTn*Gn];   // quad layout: [r][jh*4 + gate]
__device__ __align__(256) float d_bvecM[3*Gn];        // quad layout: bvec | M2row0 | M2row1
__device__ __align__(256) float d_b1p[Gn];            // quad layout bih1+bhh1
// weights: [pcol2][k] fp16, pcol2 = ((gate>>1)<<11) | (jh<<1) | (gate&1)
__device__ __align__(256) __half d_Whh0h[Gn*Hn];
__device__ __align__(256) __half d_Whh0l[Gn*Hn];
__device__ __align__(256) __half d_Wih1h[Gn*Hn];
__device__ __align__(256) __half d_Wih1l[Gn*Hn];
__device__ __align__(256) __half d_Whh1h[Gn*Hn];
__device__ __align__(256) __half d_Whh1l[Gn*Hn];
__device__ __align__(256) __half d_h0h[2][BTn*Hn];    // [step parity]
__device__ __align__(256) __half d_h1h[2][BTn*Hn];
__device__ __align__(256) float d_h1f[BTn*Hn];
__device__ __align__(256) float d_c0[BTn*Hn];
__device__ __align__(256) float d_c1[BTn*Hn];
__device__ __align__(256) float d_cur[BTn*2];

__device__ __forceinline__ float sigf(float x){ return 1.f/(1.f+__expf(-x)); }

__device__ __forceinline__ uint32_t smem_u32(const void* p){
  uint32_t a; asm("{ .reg .u64 t; cvta.to.shared.u64 t, %1; cvt.u32.u64 %0, t; }" : "=r"(a) : "l"(p));
  return a;
}

#define MMA16816(d, a, b) \
  asm volatile("mma.sync.aligned.m16n8k16.row.col.f32.f16.f16.f32 " \
    "{%0,%1,%2,%3}, {%4,%5,%6,%7}, {%8,%9}, {%0,%1,%2,%3};" \
    : "+f"((d)[0]), "+f"((d)[1]), "+f"((d)[2]), "+f"((d)[3]) \
    : "r"((a)[0]), "r"((a)[1]), "r"((a)[2]), "r"((a)[3]), "r"((b)[0]), "r"((b)[1]))

// ============================ init ============================
__global__ void k_init(const float* __restrict__ sos){
  int idx = blockIdx.x*blockDim.x + threadIdx.x;
  if (idx < BTn*Hn){
    d_c0[idx]=0.f; d_c1[idx]=0.f;
    __half z = __float2half(0.f);
    d_h0h[0][idx]=z; d_h0h[1][idx]=z; d_h1h[0][idx]=z; d_h1h[1][idx]=z;
  }
  if (idx < BTn){ d_cur[idx*2+0]=sos[0]; d_cur[idx*2+1]=sos[1]; }
}

// ============ weight convert: transpose + pcol2 permute + fp16 hi/lo split ============
__global__ void k_wconv(const float* __restrict__ W0, const float* __restrict__ W1,
                        const float* __restrict__ W2){
  __shared__ float ts[64][65];
  const float* W = (blockIdx.z==0)? W0 : (blockIdx.z==1)? W1 : W2;
  __half* Dhi = (blockIdx.z==0)? d_Whh0h : (blockIdx.z==1)? d_Wih1h : d_Whh1h;
  __half* Dlo = (blockIdx.z==0)? d_Whh0l : (blockIdx.z==1)? d_Wih1l : d_Whh1l;
  int c0 = blockIdx.x*64, k0 = blockIdx.y*64;
  int tx = threadIdx.x, ty = threadIdx.y;
  #pragma unroll
  for (int i=0;i<8;i++){
    int kl = ty + i*8;
    ts[kl][tx] = W[(size_t)(k0+kl)*Gn + c0 + tx];
  }
  __syncthreads();
  #pragma unroll
  for (int i=0;i<8;i++){
    int lc = ty + i*8;
    int c = c0 + lc;
    int q = c >> 10, jh = c & 1023;
    int pcol = ((q>>1)<<11) | (jh<<1) | (q&1);
    float w = ts[tx][lc];
    __half hi = __float2half_rn(w);
    Dhi[(size_t)pcol*Hn + k0 + tx] = hi;
    Dlo[(size_t)pcol*Hn + k0 + tx] = __float2half_rn(w - __half2float(hi));
  }
}

// ======== bvec/M2/b1 precompute (quad layout: jh*4+gate) ========
__global__ void k_prep(const float* __restrict__ Wih0, const float* __restrict__ bi,
                       const float* __restrict__ Wi,   const float* __restrict__ bih0,
                       const float* __restrict__ bhh0, const float* __restrict__ bih1,
                       const float* __restrict__ bhh1){
  int j = blockIdx.x*blockDim.x + threadIdx.x;   // 0..4095 original col
  float ab=0.f, a0=0.f, a1=0.f;
  for (int k=0;k<Hn;k++){
    float w = Wih0[(size_t)k*Gn + j];
    ab = fmaf(bi[k],    w, ab);
    a0 = fmaf(Wi[k],    w, a0);
    a1 = fmaf(Wi[Hn+k], w, a1);
  }
  int pcol = ((j & 1023) << 2) | (j >> 10);     // quad layout
  d_bvecM[pcol]        = bih0[j] + bhh0[j] + ab;
  d_bvecM[Gn+pcol]     = a0;
  d_bvecM[2*Gn+pcol]   = a1;
  d_b1p[pcol]          = bih1[j] + bhh1[j];
}

// ============ one-time fp32 GEMM (cond and condG0p) ============
#define AS_LD 132
template<int MODE>
__global__ __launch_bounds__(256) void gemm128(const float* __restrict__ Aext,
    const float* __restrict__ W, const float* __restrict__ biasExt, int N, int K)
{
  __shared__ float As[16*AS_LD];
  __shared__ float Ws[16*AS_LD];
  const int m0 = blockIdx.y*128, n0 = blockIdx.x*128;
  const int tid = threadIdx.x;
  const int trow = tid>>4, tcol = tid&15;
  float acc[8][8];
  #pragma unroll
  for(int i=0;i<8;i++){
    #pragma unroll
    for(int j=0;j<8;j++) acc[i][j]=0.f;
  }
  const float* Ap = MODE ? d_cond : Aext;
  for (int k0=0;k0<K;k0+=16){
    #pragma unroll
    for (int i=0;i<2;i++){
      int f = tid + i*256;
      int r = f>>2, c = f&3;
      float4 v = *(const float4*)(Ap + (size_t)(m0+r)*K + k0 + c*4);
      As[(c*4+0)*AS_LD + r]=v.x; As[(c*4+1)*AS_LD + r]=v.y;
      As[(c*4+2)*AS_LD + r]=v.z; As[(c*4+3)*AS_LD + r]=v.w;
    }
    #pragma unroll
    for (int i=0;i<2;i++){
      int f = tid + i*256;
      int kr = f>>5, nc = f&31;
      *(float4*)(&Ws[kr*AS_LD + nc*4]) = *(const float4*)(W + (size_t)(k0+kr)*N + n0 + nc*4);
    }
    __syncthreads();
    #pragma unroll
    for (int kk=0;kk<16;kk++){
      float a[8], b[8];
      *(float4*)(a)   = *(const float4*)(&As[kk*AS_LD + trow*8]);
      *(float4*)(a+4) = *(const float4*)(&As[kk*AS_LD + trow*8+4]);
      *(float4*)(b)   = *(const float4*)(&Ws[kk*AS_LD + tcol*8]);
      *(float4*)(b+4) = *(const float4*)(&Ws[kk*AS_LD + tcol*8+4]);
      #pragma unroll
      for(int i=0;i<8;i++){
        #pragma unroll
        for(int j=0;j<8;j++) acc[i][j] = fmaf(a[i], b[j], acc[i][j]);
      }
    }
    __syncthreads();
  }
  #pragma unroll
  for (int i=0;i<8;i++){
    int r = m0 + trow*8 + i;
    #pragma unroll
    for (int j=0;j<8;j++){
      int col = n0 + tcol*8 + j;
      float v = acc[i][j];
      if (MODE==0){
        v += biasExt[col];
        d_cond[(size_t)r*N + col] = v;
      } else {
        int pcol = ((col & 1023) << 2) | (col >> 10);
        v += d_bvecM[pcol];
        d_condG0p[(size_t)r*N + pcol] = v;
      }
    }
  }
}

// ============================ HMMA step GEMM + fused LSTM cell ============================
// CTA tile: M=128, N=128 (pcol2 cols [nb*64, nb*64+64) ∪ [2048+nb*64, ...))
// Stage: A 16KB | Whi 16KB | Wlo 16KB = 48KB, double-buffered (96KB)
#define STAGE_BYTES 49152
#define GEMM_SMEM (2*STAGE_BYTES)

__device__ __forceinline__ void load_stage(uint32_t sbase, const __half* Asrc,
    const __half* Whi, const __half* Wlo, int m0, int nb, int k0, int tid){
  #pragma unroll
  for (int it=0; it<12; it++){
    int idx = it*256 + tid;
    int tile = idx >> 10;          // 0:A 1:Whi 2:Wlo
    int rem  = idx & 1023;
    int row  = rem >> 3;
    int cc   = rem & 7;
    const __half* src;
    if (tile==0) src = Asrc + (size_t)(m0+row)*Hn;
    else {
      int pr = nb*64 + row + ((row>=64)? (2048-64) : 0);
      src = (tile==1? Whi : Wlo) + (size_t)pr*Hn;
    }
    uint32_t daddr = sbase + tile*16384 + row*128 + ((cc ^ (row&7))<<4);
    const void* g = (const void*)(src + k0 + cc*8);
    asm volatile("cp.async.cg.shared.global [%0], [%1], 16;" :: "r"(daddr), "l"(g));
  }
}

__device__ __forceinline__ void compute_stage(uint32_t sbase, float acc[4][4][4],
                                              int lane, int wm, int wn){
  const uint32_t As = sbase, Bh = sbase + 16384, Bl = sbase + 32768;
  #pragma unroll
  for (int kk=0; kk<4; kk++){
    uint32_t a[4][4];
    #pragma unroll
    for (int mt=0; mt<4; mt++){
      int m = wm*64 + mt*16 + (lane & 15);
      int ch = kk*2 + (lane>>4);
      uint32_t addr = As + m*128 + ((ch ^ (m&7))<<4);
      asm volatile("ldmatrix.sync.aligned.m8n8.x4.shared.b16 {%0,%1,%2,%3}, [%4];"
        : "=r"(a[mt][0]),"=r"(a[mt][1]),"=r"(a[mt][2]),"=r"(a[mt][3]) : "r"(addr));
    }
    uint32_t bh[4][2], bl[4][2];
    #pragma unroll
    for (int nt=0; nt<4; nt++){
      int l16 = lane & 15;
      int rb = (nt<2 ? wn*16 + nt*8 : 64 + wn*16 + (nt-2)*8) + (l16 & 7);
      int ch = kk*2 + (l16>>3);
      uint32_t off = rb*128 + ((ch ^ (rb&7))<<4);
      asm volatile("ldmatrix.sync.aligned.m8n8.x2.shared.b16 {%0,%1}, [%2];"
        : "=r"(bh[nt][0]),"=r"(bh[nt][1]) : "r"(Bh + off));
      asm volatile("ldmatrix.sync.aligned.m8n8.x2.shared.b16 {%0,%1}, [%2];"
        : "=r"(bl[nt][0]),"=r"(bl[nt][1]) : "r"(Bl + off));
    }
    #pragma unroll
    for (int mt=0; mt<4; mt++){
      #pragma unroll
      for (int nt=0; nt<4; nt++){
        MMA16816(acc[mt][nt], a[mt], bh[nt]);
        MMA16816(acc[mt][nt], a[mt], bl[nt]);
      }
    }
  }
}

template<int LAYER>
__device__ __forceinline__ void chunk_src(int sbuf, int ch, const __half*& A,
    const __half*& Wh, const __half*& Wl, int& k0){
  if (LAYER==0){ A = d_h0h[sbuf^1]; Wh = d_Whh0h; Wl = d_Whh0l; k0 = ch*KC; }
  else if (ch < 16){ A = d_h0h[sbuf]; Wh = d_Wih1h; Wl = d_Wih1l; k0 = ch*KC; }
  else { A = d_h1h[sbuf^1]; Wh = d_Whh1h; Wl = d_Whh1l; k0 = (ch-16)*KC; }
}

template<int LAYER>
__global__ __launch_bounds__(256, 1) void gemm_step(int sbuf){
  extern __shared__ char smem[];
  const uint32_t sb = smem_u32(smem);
  const int tid = threadIdx.x;
  const int lane = tid & 31, wid = tid >> 5;
  const int wm = wid >> 2, wn = wid & 3;
  const int nb = blockIdx.x, m0 = blockIdx.y * 128;
  const int nch = LAYER ? 32 : 16;

  float acc[4][4][4];
  #pragma unroll
  for (int i=0;i<4;i++){
    #pragma unroll
    for (int j=0;j<4;j++){
      #pragma unroll
      for (int k=0;k<4;k++) acc[i][j][k]=0.f;
    }
  }

  // pipeline prologue
  {
    const __half *A, *Wh, *Wl; int k0;
    chunk_src<LAYER>(sbuf, 0, A, Wh, Wl, k0);
    load_stage(sb, A, Wh, Wl, m0, nb, k0, tid);
    asm volatile("cp.async.commit_group;");
  }
  for (int ch=0; ch<nch; ch++){
    if (ch+1 < nch){
      const __half *A, *Wh, *Wl; int k0;
      chunk_src<LAYER>(sbuf, ch+1, A, Wh, Wl, k0);
      load_stage(sb + ((ch+1)&1)*STAGE_BYTES, A, Wh, Wl, m0, nb, k0, tid);
      asm volatile("cp.async.commit_group;");
      asm volatile("cp.async.wait_group 1;");
    } else {
      asm volatile("cp.async.wait_group 0;");
    }
    __syncthreads();
    compute_stage(sb + (ch&1)*STAGE_BYTES, acc, lane, wm, wn);
    __syncthreads();
  }

  // ---- fused LSTM cell epilogue ----
  const int q  = lane & 3;
  const int tq = lane >> 2;
  float* cst = LAYER ? d_c1 : d_c0;
  __half* hout = LAYER ? d_h1h[sbuf] : d_h0h[sbuf];

  #pragma unroll
  for (int mt=0; mt<4; mt++){
    #pragma unroll
    for (int rr=0; rr<2; rr++){
      int r = m0 + wm*64 + mt*16 + tq + rr*8;
      float cu0 = 0.f, cu1 = 0.f;
      if (LAYER == 0){ cu0 = d_cur[2*r]; cu1 = d_cur[2*r+1]; }
      #pragma unroll
      for (int nt=0; nt<2; nt++){
        int jh = nb*32 + wn*8 + nt*4 + q;
        float vi = acc[mt][nt  ][rr*2+0];
        float vf = acc[mt][nt  ][rr*2+1];
        float vg = acc[mt][nt+2][rr*2+0];
        float vo = acc[mt][nt+2][rr*2+1];
        if (LAYER == 0){
          float4 pg = *(const float4*)&d_condG0p[(size_t)r*Gn + jh*4];
          float4 ma = *(const float4*)&d_bvecM[Gn + jh*4];
          float4 mb = *(const float4*)&d_bvecM[2*Gn + jh*4];
          vi += pg.x + cu0*ma.x + cu1*mb.x;
          vf += pg.y + cu0*ma.y + cu1*mb.y;
          vg += pg.z + cu0*ma.z + cu1*mb.z;
          vo += pg.w + cu0*ma.w + cu1*mb.w;
        } else {
          float4 b1 = *(const float4*)&d_b1p[jh*4];
          vi += b1.x; vf += b1.y; vg += b1.z; vo += b1.w;
        }
        size_t off = (size_t)r*Hn + jh;
        float co = cst[off];
        float cn = sigf(vf)*co + sigf(vi)*tanhf(vg);
        cst[off] = cn;
        float h = sigf(vo)*tanhf(cn);
        if (LAYER) d_h1f[off] = h;
        hout[off] = __float2half_rn(h);
      }
    }
  }
}

// ============ output projection + feedback ============
__global__ __launch_bounds__(128) void k_logit(const float* __restrict__ Wo,
      const float* __restrict__ bo, float* __restrict__ out, int s){
  __shared__ float red[128*NCn];
  __shared__ float lg[NCn];
  int r = blockIdx.x;
  const float* hr = d_h1f + (size_t)r*Hn;
  float acc[NCn];
  #pragma unroll
  for(int c=0;c<NCn;c++) acc[c]=0.f;
  for (int k=threadIdx.x; k<Hn; k+=128){
    float a = hr[k];
    const float* w = Wo + (size_t)k*NCn;
    #pragma unroll
    for(int c=0;c<NCn;c++) acc[c] = fmaf(a, w[c], acc[c]);
  }
  #pragma unroll
  for(int c=0;c<NCn;c++) red[threadIdx.x*NCn + c] = acc[c];
  __syncthreads();
  if (threadIdx.x < NCn){
    float sv = bo[threadIdx.x];
    for (int t=0;t<128;t++) sv += red[t*NCn + threadIdx.x];
    int b = r>>6, tt = r&63;
    out[ (((size_t)b*NCn + threadIdx.x)*64 + tt)*128 + s ] = sv;
    lg[threadIdx.x] = sv;
  }
  __syncthreads();
  if (threadIdx.x==0){
    d_cur[r*2] = (lg[0] > 0.f) ? 1.f : 0.f;
    float best = lg[1]; int bidx = 0;
    #pragma unroll
    for (int c=2;c<NCn;c++){ if (lg[c] > best){ best=lg[c]; bidx=c-1; } }
    d_cur[r*2+1] = (float)bidx * (1.f/(VBn-1));
  }
}

// ============================ launch ============================
extern "C" void kernel_launch(void* const* d_in, const int* in_sizes, int n_in,
                              void* d_out, int out_size){
  const float* x    = (const float*)d_in[0];
  const float* sos  = (const float*)d_in[1];
  const float* Wc   = (const float*)d_in[2];
  const float* bc   = (const float*)d_in[3];
  const float* Wi   = (const float*)d_in[4];
  const float* bi   = (const float*)d_in[5];
  const float* Wih0 = (const float*)d_in[6];
  const float* Whh0 = (const float*)d_in[7];
  const float* bih0 = (const float*)d_in[8];
  const float* bhh0 = (const float*)d_in[9];
  const float* Wih1 = (const float*)d_in[10];
  const float* Whh1 = (const float*)d_in[11];
  const float* bih1 = (const float*)d_in[12];
  const float* bhh1 = (const float*)d_in[13];
  const float* Wo   = (const float*)d_in[14];
  const float* bo   = (const float*)d_in[15];
  float* out = (float*)d_out;

  cudaFuncSetAttribute(gemm_step<0>, cudaFuncAttributeMaxDynamicSharedMemorySize, GEMM_SMEM);
  cudaFuncSetAttribute(gemm_step<1>, cudaFuncAttributeMaxDynamicSharedMemorySize, GEMM_SMEM);

  k_init<<<(BTn*Hn+255)/256, 256>>>(sos);
  k_wconv<<<dim3(Gn/64, Hn/64, 3), dim3(64,8)>>>(Whh0, Wih1, Whh1);
  k_prep<<<Gn/128, 128>>>(Wih0, bi, Wi, bih0, bhh0, bih1, bhh1);
  gemm128<0><<<dim3(Hn/128, BTn/128), 256>>>(x, Wc, bc, Hn, En);
  gemm128<1><<<dim3(Gn/128, BTn/128), 256>>>(nullptr, Wih0 + (size_t)Hn*Gn, nullptr, Gn, Hn);

  for (int s = 0; s < NSTEPS; s++){
    gemm_step<0><<<dim3(32,4), 256, GEMM_SMEM>>>(s & 1);
    gemm_step<1><<<dim3(32,4), 256, GEMM_SMEM>>>(s & 1);
    k_logit<<<BTn, 128>>>(Wo, bo, out, s);
  }
}

// round 6
// speedup vs baseline: 4.9781x; 1.3435x over previous
#include <cuda_runtime.h>
#include <cuda_fp16.h>
#include <math.h>
#include <stdint.h>

#define BTn 512
#define En  512
#define Hn  1024
#define Gn  4096
#define NCn 33
#define VBn 32
#define NSTEPS 128
#define KC 64

// ============================ device globals ============================
__device__ __align__(256) float d_cond[BTn*Hn];
__device__ __align__(256) float d_condG0p[BTn*Gn];   // quad layout: [r][jh*4 + gate]
__device__ __align__(256) float d_bvecM[3*Gn];        // quad layout: bvec | M2row0 | M2row1
__device__ __align__(256) float d_b1p[Gn];            // quad layout bih1+bhh1
// weights: [pcol2][k] fp16, pcol2 = ((gate>>1)<<11) | (jh<<1) | (gate&1)
__device__ __align__(256) __half d_Whh0h[Gn*Hn];
__device__ __align__(256) __half d_Wih1h[Gn*Hn];
__device__ __align__(256) __half d_Whh1h[Gn*Hn];
__device__ __align__(256) __half d_h0h[2][BTn*Hn];    // [step parity]
__device__ __align__(256) __half d_h1h[2][BTn*Hn];
__device__ __align__(256) float d_h1f[BTn*Hn];
__device__ __align__(256) float d_c0[BTn*Hn];
__device__ __align__(256) float d_c1[BTn*Hn];
__device__ __align__(256) float d_cur[BTn*2];

__device__ __forceinline__ float sigf(float x){ return 1.f/(1.f+__expf(-x)); }

__device__ __forceinline__ uint32_t smem_u32(const void* p){
  uint32_t a; asm("{ .reg .u64 t; cvta.to.shared.u64 t, %1; cvt.u32.u64 %0, t; }" : "=r"(a) : "l"(p));
  return a;
}

#define MMA16816(d, a, b) \
  asm volatile("mma.sync.aligned.m16n8k16.row.col.f32.f16.f16.f32 " \
    "{%0,%1,%2,%3}, {%4,%5,%6,%7}, {%8,%9}, {%0,%1,%2,%3};" \
    : "+f"((d)[0]), "+f"((d)[1]), "+f"((d)[2]), "+f"((d)[3]) \
    : "r"((a)[0]), "r"((a)[1]), "r"((a)[2]), "r"((a)[3]), "r"((b)[0]), "r"((b)[1]))

// ============================ init ============================
__global__ void k_init(const float* __restrict__ sos){
  int idx = blockIdx.x*blockDim.x + threadIdx.x;
  if (idx < BTn*Hn){
    d_c0[idx]=0.f; d_c1[idx]=0.f;
    __half z = __float2half(0.f);
    d_h0h[0][idx]=z; d_h0h[1][idx]=z; d_h1h[0][idx]=z; d_h1h[1][idx]=z;
  }
  if (idx < BTn){ d_cur[idx*2+0]=sos[0]; d_cur[idx*2+1]=sos[1]; }
}

// ============ weight convert: transpose + pcol2 permute + fp16 ============
__global__ void k_wconv(const float* __restrict__ W0, const float* __restrict__ W1,
                        const float* __restrict__ W2){
  __shared__ float ts[64][65];
  const float* W = (blockIdx.z==0)? W0 : (blockIdx.z==1)? W1 : W2;
  __half* Dhi = (blockIdx.z==0)? d_Whh0h : (blockIdx.z==1)? d_Wih1h : d_Whh1h;
  int c0 = blockIdx.x*64, k0 = blockIdx.y*64;
  int tx = threadIdx.x, ty = threadIdx.y;
  #pragma unroll
  for (int i=0;i<8;i++){
    int kl = ty + i*8;
    ts[kl][tx] = W[(size_t)(k0+kl)*Gn + c0 + tx];
  }
  __syncthreads();
  #pragma unroll
  for (int i=0;i<8;i++){
    int lc = ty + i*8;
    int c = c0 + lc;
    int q = c >> 10, jh = c & 1023;
    int pcol = ((q>>1)<<11) | (jh<<1) | (q&1);
    Dhi[(size_t)pcol*Hn + k0 + tx] = __float2half_rn(ts[tx][lc]);
  }
}

// ======== bvec/M2/b1 precompute (quad layout: jh*4+gate) ========
__global__ void k_prep(const float* __restrict__ Wih0, const float* __restrict__ bi,
                       const float* __restrict__ Wi,   const float* __restrict__ bih0,
                       const float* __restrict__ bhh0, const float* __restrict__ bih1,
                       const float* __restrict__ bhh1){
  int j = blockIdx.x*blockDim.x + threadIdx.x;   // 0..4095 original col
  float ab=0.f, a0=0.f, a1=0.f;
  for (int k=0;k<Hn;k++){
    float w = Wih0[(size_t)k*Gn + j];
    ab = fmaf(bi[k],    w, ab);
    a0 = fmaf(Wi[k],    w, a0);
    a1 = fmaf(Wi[Hn+k], w, a1);
  }
  int pcol = ((j & 1023) << 2) | (j >> 10);     // quad layout
  d_bvecM[pcol]        = bih0[j] + bhh0[j] + ab;
  d_bvecM[Gn+pcol]     = a0;
  d_bvecM[2*Gn+pcol]   = a1;
  d_b1p[pcol]          = bih1[j] + bhh1[j];
}

// ============ one-time fp32 GEMM (cond and condG0p) ============
#define AS_LD 132
template<int MODE>
__global__ __launch_bounds__(256) void gemm128(const float* __restrict__ Aext,
    const float* __restrict__ W, const float* __restrict__ biasExt, int N, int K)
{
  __shared__ float As[16*AS_LD];
  __shared__ float Ws[16*AS_LD];
  const int m0 = blockIdx.y*128, n0 = blockIdx.x*128;
  const int tid = threadIdx.x;
  const int trow = tid>>4, tcol = tid&15;
  float acc[8][8];
  #pragma unroll
  for(int i=0;i<8;i++){
    #pragma unroll
    for(int j=0;j<8;j++) acc[i][j]=0.f;
  }
  const float* Ap = MODE ? d_cond : Aext;
  for (int k0=0;k0<K;k0+=16){
    #pragma unroll
    for (int i=0;i<2;i++){
      int f = tid + i*256;
      int r = f>>2, c = f&3;
      float4 v = *(const float4*)(Ap + (size_t)(m0+r)*K + k0 + c*4);
      As[(c*4+0)*AS_LD + r]=v.x; As[(c*4+1)*AS_LD + r]=v.y;
      As[(c*4+2)*AS_LD + r]=v.z; As[(c*4+3)*AS_LD + r]=v.w;
    }
    #pragma unroll
    for (int i=0;i<2;i++){
      int f = tid + i*256;
      int kr = f>>5, nc = f&31;
      *(float4*)(&Ws[kr*AS_LD + nc*4]) = *(const float4*)(W + (size_t)(k0+kr)*N + n0 + nc*4);
    }
    __syncthreads();
    #pragma unroll
    for (int kk=0;kk<16;kk++){
      float a[8], b[8];
      *(float4*)(a)   = *(const float4*)(&As[kk*AS_LD + trow*8]);
      *(float4*)(a+4) = *(const float4*)(&As[kk*AS_LD + trow*8+4]);
      *(float4*)(b)   = *(const float4*)(&Ws[kk*AS_LD + tcol*8]);
      *(float4*)(b+4) = *(const float4*)(&Ws[kk*AS_LD + tcol*8+4]);
      #pragma unroll
      for(int i=0;i<8;i++){
        #pragma unroll
        for(int j=0;j<8;j++) acc[i][j] = fmaf(a[i], b[j], acc[i][j]);
      }
    }
    __syncthreads();
  }
  #pragma unroll
  for (int i=0;i<8;i++){
    int r = m0 + trow*8 + i;
    #pragma unroll
    for (int j=0;j<8;j++){
      int col = n0 + tcol*8 + j;
      float v = acc[i][j];
      if (MODE==0){
        v += biasExt[col];
        d_cond[(size_t)r*N + col] = v;
      } else {
        int pcol = ((col & 1023) << 2) | (col >> 10);
        v += d_bvecM[pcol];
        d_condG0p[(size_t)r*N + pcol] = v;
      }
    }
  }
}

// ============================ HMMA step GEMM + fused LSTM cell ============================
// CTA tile: M=128, N=128 pcol2 cols [nb*64, nb*64+64) ∪ [2048+nb*64, ...)
// Stage: A 16KB | W 16KB = 32KB, 3-stage ring (96KB)
#define STAGE_BYTES 32768
#define NSTAGE 3
#define GEMM_SMEM (NSTAGE*STAGE_BYTES)

__device__ __forceinline__ void load_stage(uint32_t sbase, const __half* Asrc,
    const __half* Whi, int m0, int nb, int k0, int tid){
  #pragma unroll
  for (int it=0; it<8; it++){
    int idx = it*256 + tid;
    int tile = idx >> 10;          // 0:A 1:W
    int rem  = idx & 1023;
    int row  = rem >> 3;
    int cc   = rem & 7;
    const __half* src;
    if (tile==0) src = Asrc + (size_t)(m0+row)*Hn;
    else {
      int pr = nb*64 + row + ((row>=64)? (2048-64) : 0);
      src = Whi + (size_t)pr*Hn;
    }
    uint32_t daddr = sbase + tile*16384 + row*128 + ((cc ^ (row&7))<<4);
    const void* g = (const void*)(src + k0 + cc*8);
    asm volatile("cp.async.cg.shared.global [%0], [%1], 16;" :: "r"(daddr), "l"(g));
  }
}

__device__ __forceinline__ void compute_stage(uint32_t sbase, float acc[4][4][4],
                                              int lane, int wm, int wn){
  const uint32_t As = sbase, Bh = sbase + 16384;
  #pragma unroll
  for (int kk=0; kk<4; kk++){
    uint32_t a[4][4];
    #pragma unroll
    for (int mt=0; mt<4; mt++){
      int m = wm*64 + mt*16 + (lane & 15);
      int ch = kk*2 + (lane>>4);
      uint32_t addr = As + m*128 + ((ch ^ (m&7))<<4);
      asm volatile("ldmatrix.sync.aligned.m8n8.x4.shared.b16 {%0,%1,%2,%3}, [%4];"
        : "=r"(a[mt][0]),"=r"(a[mt][1]),"=r"(a[mt][2]),"=r"(a[mt][3]) : "r"(addr));
    }
    uint32_t bh[4][2];
    #pragma unroll
    for (int nt=0; nt<4; nt++){
      int l16 = lane & 15;
      int rb = (nt<2 ? wn*16 + nt*8 : 64 + wn*16 + (nt-2)*8) + (l16 & 7);
      int ch = kk*2 + (l16>>3);
      uint32_t off = rb*128 + ((ch ^ (rb&7))<<4);
      asm volatile("ldmatrix.sync.aligned.m8n8.x2.shared.b16 {%0,%1}, [%2];"
        : "=r"(bh[nt][0]),"=r"(bh[nt][1]) : "r"(Bh + off));
    }
    #pragma unroll
    for (int mt=0; mt<4; mt++){
      #pragma unroll
      for (int nt=0; nt<4; nt++){
        MMA16816(acc[mt][nt], a[mt], bh[nt]);
      }
    }
  }
}

template<int LAYER>
__device__ __forceinline__ void chunk_src(int sbuf, int ch, const __half*& A,
    const __half*& Wh, int& k0){
  if (LAYER==0){ A = d_h0h[sbuf^1]; Wh = d_Whh0h; k0 = ch*KC; }
  else if (ch < 16){ A = d_h0h[sbuf]; Wh = d_Wih1h; k0 = ch*KC; }
  else { A = d_h1h[sbuf^1]; Wh = d_Whh1h; k0 = (ch-16)*KC; }
}

template<int LAYER>
__global__ __launch_bounds__(256, 1) void gemm_step(int sbuf){
  extern __shared__ char smem[];
  const uint32_t sb = smem_u32(smem);
  const int tid = threadIdx.x;
  const int lane = tid & 31, wid = tid >> 5;
  const int wm = wid >> 2, wn = wid & 3;
  const int nb = blockIdx.x, m0 = blockIdx.y * 128;
  const int nch = LAYER ? 32 : 16;

  float acc[4][4][4];
  #pragma unroll
  for (int i=0;i<4;i++){
    #pragma unroll
    for (int j=0;j<4;j++){
      #pragma unroll
      for (int k=0;k<4;k++) acc[i][j][k]=0.f;
    }
  }

  // pipeline prologue: stages 0 and 1
  #pragma unroll
  for (int p=0;p<2;p++){
    const __half *A, *Wh; int k0;
    chunk_src<LAYER>(sbuf, p, A, Wh, k0);
    load_stage(sb + p*STAGE_BYTES, A, Wh, m0, nb, k0, tid);
    asm volatile("cp.async.commit_group;");
  }
  for (int ch=0; ch<nch; ch++){
    asm volatile("cp.async.wait_group 1;");
    __syncthreads();     // data visible + all warps done reading stage (ch-1)%3
    if (ch+2 < nch){
      const __half *A, *Wh; int k0;
      chunk_src<LAYER>(sbuf, ch+2, A, Wh, k0);
      load_stage(sb + ((ch+2)%NSTAGE)*STAGE_BYTES, A, Wh, m0, nb, k0, tid);
    }
    asm volatile("cp.async.commit_group;");   // always commit (maybe empty) to keep group count uniform
    compute_stage(sb + (ch%NSTAGE)*STAGE_BYTES, acc, lane, wm, wn);
  }

  // ---- fused LSTM cell epilogue ----
  const int q  = lane & 3;
  const int tq = lane >> 2;
  float* cst = LAYER ? d_c1 : d_c0;
  __half* hout = LAYER ? d_h1h[sbuf] : d_h0h[sbuf];

  #pragma unroll
  for (int mt=0; mt<4; mt++){
    #pragma unroll
    for (int rr=0; rr<2; rr++){
      int r = m0 + wm*64 + mt*16 + tq + rr*8;
      float cu0 = 0.f, cu1 = 0.f;
      if (LAYER == 0){ cu0 = d_cur[2*r]; cu1 = d_cur[2*r+1]; }
      #pragma unroll
      for (int nt=0; nt<2; nt++){
        int jh = nb*32 + wn*8 + nt*4 + q;
        float vi = acc[mt][nt  ][rr*2+0];
        float vf = acc[mt][nt  ][rr*2+1];
        float vg = acc[mt][nt+2][rr*2+0];
        float vo = acc[mt][nt+2][rr*2+1];
        if (LAYER == 0){
          float4 pg = *(const float4*)&d_condG0p[(size_t)r*Gn + jh*4];
          float4 ma = *(const float4*)&d_bvecM[Gn + jh*4];
          float4 mb = *(const float4*)&d_bvecM[2*Gn + jh*4];
          vi += pg.x + cu0*ma.x + cu1*mb.x;
          vf += pg.y + cu0*ma.y + cu1*mb.y;
          vg += pg.z + cu0*ma.z + cu1*mb.z;
          vo += pg.w + cu0*ma.w + cu1*mb.w;
        } else {
          float4 b1 = *(const float4*)&d_b1p[jh*4];
          vi += b1.x; vf += b1.y; vg += b1.z; vo += b1.w;
        }
        size_t off = (size_t)r*Hn + jh;
        float co = cst[off];
        float cn = sigf(vf)*co + sigf(vi)*tanhf(vg);
        cst[off] = cn;
        float h = sigf(vo)*tanhf(cn);
        if (LAYER) d_h1f[off] = h;
        hout[off] = __float2half_rn(h);
      }
    }
  }
}

// ============ output projection + feedback ============
#define RLD 34
__global__ __launch_bounds__(128) void k_logit(const float* __restrict__ Wo,
      const float* __restrict__ bo, float* __restrict__ out, int s){
  __shared__ float red[128*RLD];
  __shared__ float lg[NCn];
  int r = blockIdx.x;
  const float* hr = d_h1f + (size_t)r*Hn;
  float acc[NCn];
  #pragma unroll
  for(int c=0;c<NCn;c++) acc[c]=0.f;
  for (int k=threadIdx.x; k<Hn; k+=128){
    float a = hr[k];
    const float* w = Wo + (size_t)k*NCn;
    #pragma unroll
    for(int c=0;c<NCn;c++) acc[c] = fmaf(a, w[c], acc[c]);
  }
  #pragma unroll
  for(int c=0;c<NCn;c++) red[threadIdx.x*RLD + c] = acc[c];
  __syncthreads();
  // tree reduction over 128 rows
  #pragma unroll
  for (int st=64; st>0; st>>=1){
    if (threadIdx.x < st){
      #pragma unroll
      for (int c=0;c<NCn;c++)
        red[threadIdx.x*RLD + c] += red[(threadIdx.x+st)*RLD + c];
    }
    __syncthreads();
  }
  if (threadIdx.x < NCn){
    float sv = bo[threadIdx.x] + red[threadIdx.x];
    int b = r>>6, tt = r&63;
    out[ (((size_t)b*NCn + threadIdx.x)*64 + tt)*128 + s ] = sv;
    lg[threadIdx.x] = sv;
  }
  __syncthreads();
  if (threadIdx.x==0){
    d_cur[r*2] = (lg[0] > 0.f) ? 1.f : 0.f;
    float best = lg[1]; int bidx = 0;
    #pragma unroll
    for (int c=2;c<NCn;c++){ if (lg[c] > best){ best=lg[c]; bidx=c-1; } }
    d_cur[r*2+1] = (float)bidx * (1.f/(VBn-1));
  }
}

// ============================ launch ============================
extern "C" void kernel_launch(void* const* d_in, const int* in_sizes, int n_in,
                              void* d_out, int out_size){
  const float* x    = (const float*)d_in[0];
  const float* sos  = (const float*)d_in[1];
  const float* Wc   = (const float*)d_in[2];
  const float* bc   = (const float*)d_in[3];
  const float* Wi   = (const float*)d_in[4];
  const float* bi   = (const float*)d_in[5];
  const float* Wih0 = (const float*)d_in[6];
  const float* Whh0 = (const float*)d_in[7];
  const float* bih0 = (const float*)d_in[8];
  const float* bhh0 = (const float*)d_in[9];
  const float* Wih1 = (const float*)d_in[10];
  const float* Whh1 = (const float*)d_in[11];
  const float* bih1 = (const float*)d_in[12];
  const float* bhh1 = (const float*)d_in[13];
  const float* Wo   = (const float*)d_in[14];
  const float* bo   = (const float*)d_in[15];
  float* out = (float*)d_out;

  cudaFuncSetAttribute(gemm_step<0>, cudaFuncAttributeMaxDynamicSharedMemorySize, GEMM_SMEM);
  cudaFuncSetAttribute(gemm_step<1>, cudaFuncAttributeMaxDynamicSharedMemorySize, GEMM_SMEM);

  k_init<<<(BTn*Hn+255)/256, 256>>>(sos);
  k_wconv<<<dim3(Gn/64, Hn/64, 3), dim3(64,8)>>>(Whh0, Wih1, Whh1);
  k_prep<<<Gn/128, 128>>>(Wih0, bi, Wi, bih0, bhh0, bih1, bhh1);
  gemm128<0><<<dim3(Hn/128, BTn/128), 256>>>(x, Wc, bc, Hn, En);
  gemm128<1><<<dim3(Gn/128, BTn/128), 256>>>(nullptr, Wih0 + (size_t)Hn*Gn, nullptr, Gn, Hn);

  for (int s = 0; s < NSTEPS; s++){
    gemm_step<0><<<dim3(32,4), 256, GEMM_SMEM>>>(s & 1);
    gemm_step<1><<<dim3(32,4), 256, GEMM_SMEM>>>(s & 1);
    k_logit<<<BTn, 128>>>(Wo, bo, out, s);
  }
}

// round 7
// speedup vs baseline: 5.4992x; 1.1047x over previous
#include <cuda_runtime.h>
#include <cuda_fp16.h>
#include <math.h>
#include <stdint.h>

#define BTn 512
#define En  512
#define Hn  1024
#define Gn  4096
#define NCn 33
#define VBn 32
#define NSTEPS 128
#define KC 64
#define NCTA 128

// ============================ device globals ============================
__device__ __align__(256) float d_cond[BTn*Hn];
__device__ __align__(256) float d_condG0p[BTn*Gn];   // quad layout: [r][jh*4 + gate]
__device__ __align__(256) float d_bvecM[3*Gn];        // quad: bvec | M2row0 | M2row1
__device__ __align__(256) float d_b1p[Gn];            // quad bih1+bhh1
// weights: [pcol2][k] fp16, pcol2 = ((gate>>1)<<11) | (jh<<1) | (gate&1)
__device__ __align__(256) __half d_Whh0h[Gn*Hn];
__device__ __align__(256) __half d_Wih1h[Gn*Hn];
__device__ __align__(256) __half d_Whh1h[Gn*Hn];
__device__ __align__(256) __half d_h0h[2][BTn*Hn];    // [step parity]
__device__ __align__(256) __half d_h1h[2][BTn*Hn];
__device__ __align__(256) float d_h1f[BTn*Hn];
__device__ __align__(256) float d_c0[BTn*Hn];
__device__ __align__(256) float d_c1[BTn*Hn];
__device__ __align__(256) float d_cur[BTn*2];
__device__ unsigned d_cnt;
__device__ unsigned d_flag;

__device__ __forceinline__ float sigf(float x){ return 1.f/(1.f+__expf(-x)); }

__device__ __forceinline__ uint32_t smem_u32(const void* p){
  uint32_t a; asm("{ .reg .u64 t; cvta.to.shared.u64 t, %1; cvt.u32.u64 %0, t; }" : "=r"(a) : "l"(p));
  return a;
}

#define MMA16816(d, a, b) \
  asm volatile("mma.sync.aligned.m16n8k16.row.col.f32.f16.f16.f32 " \
    "{%0,%1,%2,%3}, {%4,%5,%6,%7}, {%8,%9}, {%0,%1,%2,%3};" \
    : "+f"((d)[0]), "+f"((d)[1]), "+f"((d)[2]), "+f"((d)[3]) \
    : "r"((a)[0]), "r"((a)[1]), "r"((a)[2]), "r"((a)[3]), "r"((b)[0]), "r"((b)[1]))

// ---- grid barrier: monotonic counter + release/acquire flag ----
__device__ __forceinline__ void gridbar(unsigned target){
  __syncthreads();
  if (threadIdx.x == 0){
    __threadfence();
    unsigned old = atomicAdd(&d_cnt, 1u);
    if (old == target*NCTA - 1u){
      asm volatile("st.release.gpu.u32 [%0], %1;" :: "l"(&d_flag), "r"(target) : "memory");
    } else {
      unsigned v;
      do { asm volatile("ld.acquire.gpu.u32 %0, [%1];" : "=r"(v) : "l"(&d_flag) : "memory"); }
      while (v < target);
    }
  }
  __syncthreads();
}

// ============================ init ============================
__global__ void k_init(const float* __restrict__ sos){
  int idx = blockIdx.x*blockDim.x + threadIdx.x;
  if (idx < BTn*Hn){
    d_c0[idx]=0.f; d_c1[idx]=0.f;
    __half z = __float2half(0.f);
    d_h0h[0][idx]=z; d_h0h[1][idx]=z; d_h1h[0][idx]=z; d_h1h[1][idx]=z;
  }
  if (idx < BTn){ d_cur[idx*2+0]=sos[0]; d_cur[idx*2+1]=sos[1]; }
  if (idx == 0){ d_cnt = 0u; d_flag = 0u; }
}

// ============ weight convert: transpose + pcol2 permute + fp16 ============
__global__ void k_wconv(const float* __restrict__ W0, const float* __restrict__ W1,
                        const float* __restrict__ W2){
  __shared__ float ts[64][65];
  const float* W = (blockIdx.z==0)? W0 : (blockIdx.z==1)? W1 : W2;
  __half* Dhi = (blockIdx.z==0)? d_Whh0h : (blockIdx.z==1)? d_Wih1h : d_Whh1h;
  int c0 = blockIdx.x*64, k0 = blockIdx.y*64;
  int tx = threadIdx.x, ty = threadIdx.y;
  #pragma unroll
  for (int i=0;i<8;i++){
    int kl = ty + i*8;
    ts[kl][tx] = W[(size_t)(k0+kl)*Gn + c0 + tx];
  }
  __syncthreads();
  #pragma unroll
  for (int i=0;i<8;i++){
    int lc = ty + i*8;
    int c = c0 + lc;
    int q = c >> 10, jh = c & 1023;
    int pcol = ((q>>1)<<11) | (jh<<1) | (q&1);
    Dhi[(size_t)pcol*Hn + k0 + tx] = __float2half_rn(ts[tx][lc]);
  }
}

// ======== bvec/M2/b1 precompute (quad layout: jh*4+gate) ========
__global__ void k_prep(const float* __restrict__ Wih0, const float* __restrict__ bi,
                       const float* __restrict__ Wi,   const float* __restrict__ bih0,
                       const float* __restrict__ bhh0, const float* __restrict__ bih1,
                       const float* __restrict__ bhh1){
  int j = blockIdx.x*blockDim.x + threadIdx.x;
  float ab=0.f, a0=0.f, a1=0.f;
  for (int k=0;k<Hn;k++){
    float w = Wih0[(size_t)k*Gn + j];
    ab = fmaf(bi[k],    w, ab);
    a0 = fmaf(Wi[k],    w, a0);
    a1 = fmaf(Wi[Hn+k], w, a1);
  }
  int pcol = ((j & 1023) << 2) | (j >> 10);
  d_bvecM[pcol]        = bih0[j] + bhh0[j] + ab;
  d_bvecM[Gn+pcol]     = a0;
  d_bvecM[2*Gn+pcol]   = a1;
  d_b1p[pcol]          = bih1[j] + bhh1[j];
}

// ============ one-time fp32 GEMM (cond and condG0p) ============
#define AS_LD 132
template<int MODE>
__global__ __launch_bounds__(256) void gemm128(const float* __restrict__ Aext,
    const float* __restrict__ W, const float* __restrict__ biasExt, int N, int K)
{
  __shared__ float As[16*AS_LD];
  __shared__ float Ws[16*AS_LD];
  const int m0 = blockIdx.y*128, n0 = blockIdx.x*128;
  const int tid = threadIdx.x;
  const int trow = tid>>4, tcol = tid&15;
  float acc[8][8];
  #pragma unroll
  for(int i=0;i<8;i++){
    #pragma unroll
    for(int j=0;j<8;j++) acc[i][j]=0.f;
  }
  const float* Ap = MODE ? d_cond : Aext;
  for (int k0=0;k0<K;k0+=16){
    #pragma unroll
    for (int i=0;i<2;i++){
      int f = tid + i*256;
      int r = f>>2, c = f&3;
      float4 v = *(const float4*)(Ap + (size_t)(m0+r)*K + k0 + c*4);
      As[(c*4+0)*AS_LD + r]=v.x; As[(c*4+1)*AS_LD + r]=v.y;
      As[(c*4+2)*AS_LD + r]=v.z; As[(c*4+3)*AS_LD + r]=v.w;
    }
    #pragma unroll
    for (int i=0;i<2;i++){
      int f = tid + i*256;
      int kr = f>>5, nc = f&31;
      *(float4*)(&Ws[kr*AS_LD + nc*4]) = *(const float4*)(W + (size_t)(k0+kr)*N + n0 + nc*4);
    }
    __syncthreads();
    #pragma unroll
    for (int kk=0;kk<16;kk++){
      float a[8], b[8];
      *(float4*)(a)   = *(const float4*)(&As[kk*AS_LD + trow*8]);
      *(float4*)(a+4) = *(const float4*)(&As[kk*AS_LD + trow*8+4]);
      *(float4*)(b)   = *(const float4*)(&Ws[kk*AS_LD + tcol*8]);
      *(float4*)(b+4) = *(const float4*)(&Ws[kk*AS_LD + tcol*8+4]);
      #pragma unroll
      for(int i=0;i<8;i++){
        #pragma unroll
        for(int j=0;j<8;j++) acc[i][j] = fmaf(a[i], b[j], acc[i][j]);
      }
    }
    __syncthreads();
  }
  #pragma unroll
  for (int i=0;i<8;i++){
    int r = m0 + trow*8 + i;
    #pragma unroll
    for (int j=0;j<8;j++){
      int col = n0 + tcol*8 + j;
      float v = acc[i][j];
      if (MODE==0){
        v += biasExt[col];
        d_cond[(size_t)r*N + col] = v;
      } else {
        int pcol = ((col & 1023) << 2) | (col >> 10);
        v += d_bvecM[pcol];
        d_condG0p[(size_t)r*N + pcol] = v;
      }
    }
  }
}

// ============================ persistent step kernel ============================
#define STAGE_BYTES 32768
#define NSTAGE 3
#define GEMM_SMEM (NSTAGE*STAGE_BYTES)

__device__ __forceinline__ void load_stage(uint32_t sbase, const __half* Asrc,
    const __half* Whi, int m0, int nb, int k0, int tid){
  #pragma unroll
  for (int it=0; it<8; it++){
    int idx = it*256 + tid;
    int tile = idx >> 10;          // 0:A 1:W
    int rem  = idx & 1023;
    int row  = rem >> 3;
    int cc   = rem & 7;
    const __half* src;
    if (tile==0) src = Asrc + (size_t)(m0+row)*Hn;
    else {
      int pr = nb*64 + row + ((row>=64)? (2048-64) : 0);
      src = Whi + (size_t)pr*Hn;
    }
    uint32_t daddr = sbase + tile*16384 + row*128 + ((cc ^ (row&7))<<4);
    const void* g = (const void*)(src + k0 + cc*8);
    asm volatile("cp.async.cg.shared.global [%0], [%1], 16;" :: "r"(daddr), "l"(g));
  }
}

__device__ __forceinline__ void compute_stage(uint32_t sbase, float acc[4][4][4],
                                              int lane, int wm, int wn){
  const uint32_t As = sbase, Bh = sbase + 16384;
  #pragma unroll
  for (int kk=0; kk<4; kk++){
    uint32_t a[4][4];
    #pragma unroll
    for (int mt=0; mt<4; mt++){
      int m = wm*64 + mt*16 + (lane & 15);
      int ch = kk*2 + (lane>>4);
      uint32_t addr = As + m*128 + ((ch ^ (m&7))<<4);
      asm volatile("ldmatrix.sync.aligned.m8n8.x4.shared.b16 {%0,%1,%2,%3}, [%4];"
        : "=r"(a[mt][0]),"=r"(a[mt][1]),"=r"(a[mt][2]),"=r"(a[mt][3]) : "r"(addr));
    }
    uint32_t bh[4][2];
    #pragma unroll
    for (int nt=0; nt<4; nt++){
      int l16 = lane & 15;
      int rb = (nt<2 ? wn*16 + nt*8 : 64 + wn*16 + (nt-2)*8) + (l16 & 7);
      int ch = kk*2 + (l16>>3);
      uint32_t off = rb*128 + ((ch ^ (rb&7))<<4);
      asm volatile("ldmatrix.sync.aligned.m8n8.x2.shared.b16 {%0,%1}, [%2];"
        : "=r"(bh[nt][0]),"=r"(bh[nt][1]) : "r"(Bh + off));
    }
    #pragma unroll
    for (int mt=0; mt<4; mt++){
      #pragma unroll
      for (int nt=0; nt<4; nt++){
        MMA16816(acc[mt][nt], a[mt], bh[nt]);
      }
    }
  }
}

template<int LAYER>
__device__ __forceinline__ void chunk_src(int sbuf, int ch, const __half*& A,
    const __half*& Wh, int& k0){
  if (LAYER==0){ A = d_h0h[sbuf^1]; Wh = d_Whh0h; k0 = ch*KC; }
  else if (ch < 16){ A = d_h0h[sbuf]; Wh = d_Wih1h; k0 = ch*KC; }
  else { A = d_h1h[sbuf^1]; Wh = d_Whh1h; k0 = (ch-16)*KC; }
}

template<int LAYER>
__device__ __forceinline__ void gemm_phase(uint32_t sb, int sbuf, int nb, int m0,
                                           int tid, int lane, int wid){
  const int wm = wid >> 2, wn = wid & 3;
  const int nch = LAYER ? 32 : 16;

  float acc[4][4][4];
  #pragma unroll
  for (int i=0;i<4;i++){
    #pragma unroll
    for (int j=0;j<4;j++){
      #pragma unroll
      for (int k=0;k<4;k++) acc[i][j][k]=0.f;
    }
  }

  #pragma unroll
  for (int p=0;p<2;p++){
    const __half *A, *Wh; int k0;
    chunk_src<LAYER>(sbuf, p, A, Wh, k0);
    load_stage(sb + p*STAGE_BYTES, A, Wh, m0, nb, k0, tid);
    asm volatile("cp.async.commit_group;");
  }
  for (int ch=0; ch<nch; ch++){
    asm volatile("cp.async.wait_group 1;");
    __syncthreads();
    if (ch+2 < nch){
      const __half *A, *Wh; int k0;
      chunk_src<LAYER>(sbuf, ch+2, A, Wh, k0);
      load_stage(sb + ((ch+2)%NSTAGE)*STAGE_BYTES, A, Wh, m0, nb, k0, tid);
    }
    asm volatile("cp.async.commit_group;");
    compute_stage(sb + (ch%NSTAGE)*STAGE_BYTES, acc, lane, wm, wn);
  }
  asm volatile("cp.async.wait_group 0;");

  // ---- fused LSTM cell epilogue ----
  const int q  = lane & 3;
  const int tq = lane >> 2;
  float* cst = LAYER ? d_c1 : d_c0;
  __half* hout = LAYER ? d_h1h[sbuf] : d_h0h[sbuf];

  #pragma unroll
  for (int mt=0; mt<4; mt++){
    #pragma unroll
    for (int rr=0; rr<2; rr++){
      int r = m0 + (wid>>2)*64 + mt*16 + tq + rr*8;
      float cu0 = 0.f, cu1 = 0.f;
      if (LAYER == 0){ cu0 = d_cur[2*r]; cu1 = d_cur[2*r+1]; }
      #pragma unroll
      for (int nt=0; nt<2; nt++){
        int jh = nb*32 + (wid&3)*8 + nt*4 + q;
        float vi = acc[mt][nt  ][rr*2+0];
        float vf = acc[mt][nt  ][rr*2+1];
        float vg = acc[mt][nt+2][rr*2+0];
        float vo = acc[mt][nt+2][rr*2+1];
        if (LAYER == 0){
          float4 pg = *(const float4*)&d_condG0p[(size_t)r*Gn + jh*4];
          float4 ma = *(const float4*)&d_bvecM[Gn + jh*4];
          float4 mb = *(const float4*)&d_bvecM[2*Gn + jh*4];
          vi += pg.x + cu0*ma.x + cu1*mb.x;
          vf += pg.y + cu0*ma.y + cu1*mb.y;
          vg += pg.z + cu0*ma.z + cu1*mb.z;
          vo += pg.w + cu0*ma.w + cu1*mb.w;
        } else {
          float4 b1 = *(const float4*)&d_b1p[jh*4];
          vi += b1.x; vf += b1.y; vg += b1.z; vo += b1.w;
        }
        size_t off = (size_t)r*Hn + jh;
        float co = cst[off];
        float cn = sigf(vf)*co + sigf(vi)*tanhf(vg);
        cst[off] = cn;
        float h = sigf(vo)*tanhf(cn);
        if (LAYER) d_h1f[off] = h;
        hout[off] = __float2half_rn(h);
      }
    }
  }
}

// ---- logit phase: 4 rows per CTA, Wo tiled through smem ----
__device__ __forceinline__ void logit_phase(char* smem, const float* __restrict__ Wo,
    const float* __restrict__ bo, float* __restrict__ out, int s, int cta,
    int tid, int lane, int wid){
  float* wo_s = (float*)smem;                 // [128][33]
  float* red  = (float*)(smem + 17024);       // [8 warps][34]
  const int rloc = tid >> 6;                  // 0..3
  const int t64  = tid & 63;
  const int r = cta*4 + rloc;
  const float* hr = d_h1f + (size_t)r*Hn;

  float acc[NCn];
  #pragma unroll
  for (int c=0;c<NCn;c++) acc[c]=0.f;

  for (int kt=0; kt<8; kt++){
    {
      int rowi = tid >> 1, half = tid & 1;
      const float* src = Wo + (size_t)(kt*128 + rowi)*NCn;
      if (half == 0){
        #pragma unroll
        for (int c=0;c<17;c++) wo_s[rowi*NCn + c] = src[c];
      } else {
        #pragma unroll
        for (int c=17;c<NCn;c++) wo_s[rowi*NCn + c] = src[c];
      }
    }
    __syncthreads();
    #pragma unroll
    for (int i=0;i<2;i++){
      int kloc = t64*2 + i;
      float h = hr[kt*128 + kloc];
      const float* wr = &wo_s[kloc*NCn];
      #pragma unroll
      for (int c=0;c<NCn;c++) acc[c] = fmaf(h, wr[c], acc[c]);
    }
    __syncthreads();
  }
  // warp-level reduce each acc[c]
  #pragma unroll
  for (int o=16;o>0;o>>=1){
    #pragma unroll
    for (int c=0;c<NCn;c++) acc[c] += __shfl_xor_sync(0xffffffffu, acc[c], o);
  }
  if (lane == 0){
    #pragma unroll
    for (int c=0;c<NCn;c++) red[wid*34 + c] = acc[c];
  }
  __syncthreads();
  if (t64 == 0){   // one thread per row (wid even, lane 0)
    int b = r>>6, tt = r&63;
    float note = 0.f, best = -3.4e38f; int bidx = 0;
    #pragma unroll
    for (int c=0;c<NCn;c++){
      float tot = red[wid*34 + c] + red[(wid+1)*34 + c] + bo[c];
      out[(((size_t)b*NCn + c)*64 + tt)*128 + s] = tot;
      if (c == 0) note = tot;
      else if (tot > best){ best = tot; bidx = c-1; }
    }
    d_cur[r*2]   = (note > 0.f) ? 1.f : 0.f;
    d_cur[r*2+1] = (float)bidx * (1.f/(VBn-1));
  }
  __syncthreads();
}

__global__ __launch_bounds__(256, 1) void k_steps(const float* __restrict__ Wo,
    const float* __restrict__ bo, float* __restrict__ out){
  extern __shared__ char smem[];
  const uint32_t sb = smem_u32(smem);
  const int tid = threadIdx.x;
  const int lane = tid & 31, wid = tid >> 5;
  const int cta = blockIdx.x;
  const int nb = cta & 31, m0 = (cta >> 5) * 128;
  unsigned bar = 0;

  for (int s=0; s<NSTEPS; s++){
    const int sbuf = s & 1;
    gemm_phase<0>(sb, sbuf, nb, m0, tid, lane, wid);
    gridbar(++bar);
    gemm_phase<1>(sb, sbuf, nb, m0, tid, lane, wid);
    gridbar(++bar);
    logit_phase(smem, Wo, bo, out, s, cta, tid, lane, wid);
    gridbar(++bar);
  }
}

// ============================ launch ============================
extern "C" void kernel_launch(void* const* d_in, const int* in_sizes, int n_in,
                              void* d_out, int out_size){
  const float* x    = (const float*)d_in[0];
  const float* sos  = (const float*)d_in[1];
  const float* Wc   = (const float*)d_in[2];
  const float* bc   = (const float*)d_in[3];
  const float* Wi   = (const float*)d_in[4];
  const float* bi   = (const float*)d_in[5];
  const float* Wih0 = (const float*)d_in[6];
  const float* Whh0 = (const float*)d_in[7];
  const float* bih0 = (const float*)d_in[8];
  const float* bhh0 = (const float*)d_in[9];
  const float* Wih1 = (const float*)d_in[10];
  const float* Whh1 = (const float*)d_in[11];
  const float* bih1 = (const float*)d_in[12];
  const float* bhh1 = (const float*)d_in[13];
  const float* Wo   = (const float*)d_in[14];
  const float* bo   = (const float*)d_in[15];
  float* out = (float*)d_out;

  cudaFuncSetAttribute(k_steps, cudaFuncAttributeMaxDynamicSharedMemorySize, GEMM_SMEM);

  k_init<<<(BTn*Hn+255)/256, 256>>>(sos);
  k_wconv<<<dim3(Gn/64, Hn/64, 3), dim3(64,8)>>>(Whh0, Wih1, Whh1);
  k_prep<<<Gn/128, 128>>>(Wih0, bi, Wi, bih0, bhh0, bih1, bhh1);
  gemm128<0><<<dim3(Hn/128, BTn/128), 256>>>(x, Wc, bc, Hn, En);
  gemm128<1><<<dim3(Gn/128, BTn/128), 256>>>(nullptr, Wih0 + (size_t)Hn*Gn, nullptr, Gn, Hn);

  k_steps<<<NCTA, 256, GEMM_SMEM>>>(Wo, bo, out);
}

// round 8
// speedup vs baseline: 5.5745x; 1.0137x over previous
#include <cuda_runtime.h>
#include <cuda_fp16.h>
#include <math.h>
#include <stdint.h>

#define BTn 512
#define En  512
#define Hn  1024
#define Gn  4096
#define NCn 33
#define VBn 32
#define NSTEPS 128
#define KC 128
#define NCTA 128
#define LSCALE 4194304.0f
#define LINV   2.384185791015625e-07f

// ============================ device globals ============================
__device__ __align__(256) float d_cond[BTn*Hn];
__device__ __align__(256) float d_condG0p[BTn*Gn];   // quad layout: [r][jh*4 + gate]
__device__ __align__(256) float d_bvecM[3*Gn];        // quad: bvec | M2row0 | M2row1
__device__ __align__(256) float d_b1p[Gn];            // quad bih1+bhh1
// weights: [pcol2][k] fp16, pcol2 = ((gate>>1)<<11) | (jh<<1) | (gate&1)
__device__ __align__(256) __half d_Whh0h[Gn*Hn];
__device__ __align__(256) __half d_Wih1h[Gn*Hn];
__device__ __align__(256) __half d_Whh1h[Gn*Hn];
__device__ __align__(256) __half d_h0h[2][BTn*Hn];    // [step parity]
__device__ __align__(256) __half d_h1h[2][BTn*Hn];
__device__ __align__(256) float d_c0[BTn*Hn];
__device__ __align__(256) float d_c1[BTn*Hn];
__device__ __align__(256) float d_cur[BTn*2];
__device__ __align__(256) int d_intbuf[2][BTn*NCn];   // fixed-point logit partial sums
__device__ unsigned d_cnt;
__device__ unsigned d_flag;

__device__ __forceinline__ float sigf(float x){ return 1.f/(1.f+__expf(-x)); }

__device__ __forceinline__ uint32_t smem_u32(const void* p){
  uint32_t a; asm("{ .reg .u64 t; cvta.to.shared.u64 t, %1; cvt.u32.u64 %0, t; }" : "=r"(a) : "l"(p));
  return a;
}

#define MMA16816(d, a, b) \
  asm volatile("mma.sync.aligned.m16n8k16.row.col.f32.f16.f16.f32 " \
    "{%0,%1,%2,%3}, {%4,%5,%6,%7}, {%8,%9}, {%0,%1,%2,%3};" \
    : "+f"((d)[0]), "+f"((d)[1]), "+f"((d)[2]), "+f"((d)[3]) \
    : "r"((a)[0]), "r"((a)[1]), "r"((a)[2]), "r"((a)[3]), "r"((b)[0]), "r"((b)[1]))

// ---- grid barrier: monotonic counter + release/acquire flag ----
__device__ __forceinline__ void gridbar(unsigned target){
  __syncthreads();
  if (threadIdx.x == 0){
    __threadfence();
    unsigned old = atomicAdd(&d_cnt, 1u);
    if (old == target*NCTA - 1u){
      asm volatile("st.release.gpu.u32 [%0], %1;" :: "l"(&d_flag), "r"(target) : "memory");
    } else {
      unsigned v;
      do { asm volatile("ld.acquire.gpu.u32 %0, [%1];" : "=r"(v) : "l"(&d_flag) : "memory"); }
      while (v < target);
    }
  }
  __syncthreads();
}

// ============================ init ============================
__global__ void k_init(const float* __restrict__ sos){
  int idx = blockIdx.x*blockDim.x + threadIdx.x;
  if (idx < BTn*Hn){
    d_c0[idx]=0.f; d_c1[idx]=0.f;
    __half z = __float2half(0.f);
    d_h0h[0][idx]=z; d_h0h[1][idx]=z; d_h1h[0][idx]=z; d_h1h[1][idx]=z;
  }
  if (idx < BTn){ d_cur[idx*2+0]=sos[0]; d_cur[idx*2+1]=sos[1]; }
  if (idx < 2*BTn*NCn) ((int*)d_intbuf)[idx] = 0;
  if (idx == 0){ d_cnt = 0u; d_flag = 0u; }
}

// ============ weight convert: transpose + pcol2 permute + fp16 ============
__global__ void k_wconv(const float* __restrict__ W0, const float* __restrict__ W1,
                        const float* __restrict__ W2){
  __shared__ float ts[64][65];
  const float* W = (blockIdx.z==0)? W0 : (blockIdx.z==1)? W1 : W2;
  __half* Dhi = (blockIdx.z==0)? d_Whh0h : (blockIdx.z==1)? d_Wih1h : d_Whh1h;
  int c0 = blockIdx.x*64, k0 = blockIdx.y*64;
  int tx = threadIdx.x, ty = threadIdx.y;
  #pragma unroll
  for (int i=0;i<8;i++){
    int kl = ty + i*8;
    ts[kl][tx] = W[(size_t)(k0+kl)*Gn + c0 + tx];
  }
  __syncthreads();
  #pragma unroll
  for (int i=0;i<8;i++){
    int lc = ty + i*8;
    int c = c0 + lc;
    int q = c >> 10, jh = c & 1023;
    int pcol = ((q>>1)<<11) | (jh<<1) | (q&1);
    Dhi[(size_t)pcol*Hn + k0 + tx] = __float2half_rn(ts[tx][lc]);
  }
}

// ======== bvec/M2/b1 precompute (quad layout: jh*4+gate) ========
__global__ void k_prep(const float* __restrict__ Wih0, const float* __restrict__ bi,
                       const float* __restrict__ Wi,   const float* __restrict__ bih0,
                       const float* __restrict__ bhh0, const float* __restrict__ bih1,
                       const float* __restrict__ bhh1){
  int j = blockIdx.x*blockDim.x + threadIdx.x;
  float ab=0.f, a0=0.f, a1=0.f;
  for (int k=0;k<Hn;k++){
    float w = Wih0[(size_t)k*Gn + j];
    ab = fmaf(bi[k],    w, ab);
    a0 = fmaf(Wi[k],    w, a0);
    a1 = fmaf(Wi[Hn+k], w, a1);
  }
  int pcol = ((j & 1023) << 2) | (j >> 10);
  d_bvecM[pcol]        = bih0[j] + bhh0[j] + ab;
  d_bvecM[Gn+pcol]     = a0;
  d_bvecM[2*Gn+pcol]   = a1;
  d_b1p[pcol]          = bih1[j] + bhh1[j];
}

// ============ one-time fp32 GEMM (cond and condG0p) ============
#define AS_LD 132
template<int MODE>
__global__ __launch_bounds__(256) void gemm128(const float* __restrict__ Aext,
    const float* __restrict__ W, const float* __restrict__ biasExt, int N, int K)
{
  __shared__ float As[16*AS_LD];
  __shared__ float Ws[16*AS_LD];
  const int m0 = blockIdx.y*128, n0 = blockIdx.x*128;
  const int tid = threadIdx.x;
  const int trow = tid>>4, tcol = tid&15;
  float acc[8][8];
  #pragma unroll
  for(int i=0;i<8;i++){
    #pragma unroll
    for(int j=0;j<8;j++) acc[i][j]=0.f;
  }
  const float* Ap = MODE ? d_cond : Aext;
  for (int k0=0;k0<K;k0+=16){
    #pragma unroll
    for (int i=0;i<2;i++){
      int f = tid + i*256;
      int r = f>>2, c = f&3;
      float4 v = *(const float4*)(Ap + (size_t)(m0+r)*K + k0 + c*4);
      As[(c*4+0)*AS_LD + r]=v.x; As[(c*4+1)*AS_LD + r]=v.y;
      As[(c*4+2)*AS_LD + r]=v.z; As[(c*4+3)*AS_LD + r]=v.w;
    }
    #pragma unroll
    for (int i=0;i<2;i++){
      int f = tid + i*256;
      int kr = f>>5, nc = f&31;
      *(float4*)(&Ws[kr*AS_LD + nc*4]) = *(const float4*)(W + (size_t)(k0+kr)*N + n0 + nc*4);
    }
    __syncthreads();
    #pragma unroll
    for (int kk=0;kk<16;kk++){
      float a[8], b[8];
      *(float4*)(a)   = *(const float4*)(&As[kk*AS_LD + trow*8]);
      *(float4*)(a+4) = *(const float4*)(&As[kk*AS_LD + trow*8+4]);
      *(float4*)(b)   = *(const float4*)(&Ws[kk*AS_LD + tcol*8]);
      *(float4*)(b+4) = *(const float4*)(&Ws[kk*AS_LD + tcol*8+4]);
      #pragma unroll
      for(int i=0;i<8;i++){
        #pragma unroll
        for(int j=0;j<8;j++) acc[i][j] = fmaf(a[i], b[j], acc[i][j]);
      }
    }
    __syncthreads();
  }
  #pragma unroll
  for (int i=0;i<8;i++){
    int r = m0 + trow*8 + i;
    #pragma unroll
    for (int j=0;j<8;j++){
      int col = n0 + tcol*8 + j;
      float v = acc[i][j];
      if (MODE==0){
        v += biasExt[col];
        d_cond[(size_t)r*N + col] = v;
      } else {
        int pcol = ((col & 1023) << 2) | (col >> 10);
        v += d_bvecM[pcol];
        d_condG0p[(size_t)r*N + pcol] = v;
      }
    }
  }
}

// ============================ persistent step kernel ============================
#define STAGE_BYTES 65536
#define NSTAGE 3
#define SM_CUR (NSTAGE*STAGE_BYTES)       // 196608: curbuf 1024B
#define SM_WO  (SM_CUR + 1024)            // wo_s 32*34*4 = 4352B
#define SM_BO  (SM_WO + 4352)             // bos 33*4 -> 256B
#define GEMM_SMEM (SM_BO + 256)           // 202240

__device__ __forceinline__ void load_stage(uint32_t sbase, const __half* Asrc,
    const __half* Whi, int m0, int nb, int k0, int tid){
  #pragma unroll
  for (int it=0; it<16; it++){
    int idx = it*256 + tid;        // 0..4095 (16B units)
    int tile = idx >> 11;          // 0:A 1:W
    int rem  = idx & 2047;
    int row  = rem >> 4;           // 0..127
    int cc   = rem & 15;           // 16B chunk within 256B row
    const __half* src;
    if (tile==0) src = Asrc + (size_t)(m0+row)*Hn;
    else {
      int pr = nb*64 + row + ((row>=64)? (2048-64) : 0);
      src = Whi + (size_t)pr*Hn;
    }
    uint32_t daddr = sbase + tile*32768 + row*256 + ((cc ^ (row&7))<<4);
    const void* g = (const void*)(src + k0 + cc*8);
    asm volatile("cp.async.cg.shared.global [%0], [%1], 16;" :: "r"(daddr), "l"(g));
  }
}

__device__ __forceinline__ void compute_stage(uint32_t sbase, float acc[4][4][4],
                                              int lane, int wm, int wn){
  const uint32_t As = sbase, Bh = sbase + 32768;
  #pragma unroll
  for (int kk=0; kk<8; kk++){
    uint32_t a[4][4];
    #pragma unroll
    for (int mt=0; mt<4; mt++){
      int m = wm*64 + mt*16 + (lane & 15);
      int ch = kk*2 + (lane>>4);
      uint32_t addr = As + m*256 + ((ch ^ (m&7))<<4);
      asm volatile("ldmatrix.sync.aligned.m8n8.x4.shared.b16 {%0,%1,%2,%3}, [%4];"
        : "=r"(a[mt][0]),"=r"(a[mt][1]),"=r"(a[mt][2]),"=r"(a[mt][3]) : "r"(addr));
    }
    uint32_t bh[4][2];
    #pragma unroll
    for (int nt=0; nt<4; nt++){
      int l16 = lane & 15;
      int rb = (nt<2 ? wn*16 + nt*8 : 64 + wn*16 + (nt-2)*8) + (l16 & 7);
      int ch = kk*2 + (l16>>3);
      uint32_t off = rb*256 + ((ch ^ (rb&7))<<4);
      asm volatile("ldmatrix.sync.aligned.m8n8.x2.shared.b16 {%0,%1}, [%2];"
        : "=r"(bh[nt][0]),"=r"(bh[nt][1]) : "r"(Bh + off));
    }
    #pragma unroll
    for (int mt=0; mt<4; mt++){
      #pragma unroll
      for (int nt=0; nt<4; nt++){
        MMA16816(acc[mt][nt], a[mt], bh[nt]);
      }
    }
  }
}

template<int LAYER>
__device__ __forceinline__ void chunk_src(int sbuf, int ch, const __half*& A,
    const __half*& Wh, int& k0){
  if (LAYER==0){ A = d_h0h[sbuf^1]; Wh = d_Whh0h; k0 = ch*KC; }
  else if (ch < 8){ A = d_h0h[sbuf]; Wh = d_Wih1h; k0 = ch*KC; }
  else { A = d_h1h[sbuf^1]; Wh = d_Whh1h; k0 = (ch-8)*KC; }
}

template<int LAYER>
__device__ __forceinline__ void gemm_phase(char* smem, uint32_t sb, int sbuf, int nb, int m0,
    int tid, int lane, int wid, const float* curbuf, const float* wo_s, int s){
  const int wm = wid >> 2, wn = wid & 3;
  const int nch = LAYER ? 16 : 8;

  float acc[4][4][4];
  #pragma unroll
  for (int i=0;i<4;i++){
    #pragma unroll
    for (int j=0;j<4;j++){
      #pragma unroll
      for (int k=0;k<4;k++) acc[i][j][k]=0.f;
    }
  }

  #pragma unroll
  for (int p=0;p<2;p++){
    const __half *A, *Wh; int k0;
    chunk_src<LAYER>(sbuf, p, A, Wh, k0);
    load_stage(sb + p*STAGE_BYTES, A, Wh, m0, nb, k0, tid);
    asm volatile("cp.async.commit_group;");
  }
  for (int ch=0; ch<nch; ch++){
    asm volatile("cp.async.wait_group 1;");
    __syncthreads();
    if (ch+2 < nch){
      const __half *A, *Wh; int k0;
      chunk_src<LAYER>(sbuf, ch+2, A, Wh, k0);
      load_stage(sb + ((ch+2)%NSTAGE)*STAGE_BYTES, A, Wh, m0, nb, k0, tid);
    }
    asm volatile("cp.async.commit_group;");
    compute_stage(sb + (ch%NSTAGE)*STAGE_BYTES, acc, lane, wm, wn);
  }
  asm volatile("cp.async.wait_group 0;");
  __syncthreads();   // all warps done reading stages (hbuf aliases stage 0 for L1)

  // ---- fused LSTM cell epilogue ----
  const int q  = lane & 3;
  const int tq = lane >> 2;
  float* cst = LAYER ? d_c1 : d_c0;
  __half* hout = LAYER ? d_h1h[sbuf] : d_h0h[sbuf];
  float* hbuf = (float*)smem;    // stage0 region reuse (L1 only)

  #pragma unroll
  for (int mt=0; mt<4; mt++){
    #pragma unroll
    for (int rr=0; rr<2; rr++){
      int lr = wm*64 + mt*16 + tq + rr*8;
      int r = m0 + lr;
      float cu0 = 0.f, cu1 = 0.f;
      if (LAYER == 0){ cu0 = curbuf[2*lr]; cu1 = curbuf[2*lr+1]; }
      #pragma unroll
      for (int nt=0; nt<2; nt++){
        int cloc = wn*8 + nt*4 + q;          // 0..31 local column
        int jh = nb*32 + cloc;
        float vi = acc[mt][nt  ][rr*2+0];
        float vf = acc[mt][nt  ][rr*2+1];
        float vg = acc[mt][nt+2][rr*2+0];
        float vo = acc[mt][nt+2][rr*2+1];
        if (LAYER == 0){
          float4 pg = *(const float4*)&d_condG0p[(size_t)r*Gn + jh*4];
          float4 ma = *(const float4*)&d_bvecM[Gn + jh*4];
          float4 mb = *(const float4*)&d_bvecM[2*Gn + jh*4];
          vi += pg.x + cu0*ma.x + cu1*mb.x;
          vf += pg.y + cu0*ma.y + cu1*mb.y;
          vg += pg.z + cu0*ma.z + cu1*mb.z;
          vo += pg.w + cu0*ma.w + cu1*mb.w;
        } else {
          float4 b1 = *(const float4*)&d_b1p[jh*4];
          vi += b1.x; vf += b1.y; vg += b1.z; vo += b1.w;
        }
        size_t off = (size_t)r*Hn + jh;
        float co = cst[off];
        float cn = sigf(vf)*co + sigf(vi)*tanhf(vg);
        cst[off] = cn;
        float h = sigf(vo)*tanhf(cn);
        hout[off] = __float2half_rn(h);
        if (LAYER) hbuf[lr*33 + cloc] = h;
      }
    }
  }

  // ---- L1: partial logits over this CTA's 32 columns, int atomics ----
  if (LAYER == 1){
    __syncthreads();
    const int lr = tid >> 1, half = tid & 1;
    float pacc[NCn];
    #pragma unroll
    for (int c=0;c<NCn;c++) pacc[c]=0.f;
    const float* hb = hbuf + lr*33;
    #pragma unroll
    for (int cc2=0; cc2<16; cc2++){
      int col = half*16 + cc2;
      float h = hb[col];
      const float* wr = wo_s + col*34;
      #pragma unroll
      for (int o=0;o<NCn;o++) pacc[o] = fmaf(h, wr[o], pacc[o]);
    }
    int* ob = &d_intbuf[sbuf][(m0+lr)*NCn];
    #pragma unroll
    for (int o=0;o<NCn;o++){
      float v = pacc[o] + __shfl_xor_sync(0xffffffffu, pacc[o], 1);
      if (half == 0) atomicAdd(&ob[o], __float2int_rn(v*LSCALE));
    }
  }
}

__global__ __launch_bounds__(256, 1) void k_steps(const float* __restrict__ Wo,
    const float* __restrict__ bo, float* __restrict__ out){
  extern __shared__ char smem[];
  const uint32_t sb = smem_u32(smem);
  float* curbuf = (float*)(smem + SM_CUR);
  float* wo_s   = (float*)(smem + SM_WO);
  float* bos    = (float*)(smem + SM_BO);
  const int tid = threadIdx.x;
  const int lane = tid & 31, wid = tid >> 5;
  const int cta = blockIdx.x;
  const int nb = cta & 31, m0 = (cta >> 5) * 128;

  // step-invariant: cache this CTA's Wo slice + bo
  for (int i=tid; i<32*NCn; i+=256){
    int col = i/NCn, c = i - col*NCn;
    wo_s[col*34+c] = Wo[(size_t)(nb*32+col)*NCn + c];
  }
  if (tid < NCn) bos[tid] = bo[tid];
  __syncthreads();

  unsigned bar = 0;
  for (int s=0; s<NSTEPS; s++){
    const int sbuf = s & 1;
    // ---- cur read (+ out write for step s-1 by nb==0) ----
    if (tid < 128){
      int r = m0 + tid;
      float cu0, cu1;
      if (s == 0){
        cu0 = d_cur[2*r]; cu1 = d_cur[2*r+1];
      } else {
        const int* ib = &d_intbuf[(s-1)&1][r*NCn];
        int b = r>>6, tt = r&63;
        float lg0 = (float)ib[0]*LINV + bos[0];
        if (nb == 0) out[(((size_t)b*NCn + 0)*64 + tt)*128 + (s-1)] = lg0;
        float best = -3.4e38f; int bidx = 0;
        #pragma unroll
        for (int c=1;c<NCn;c++){
          float v = (float)ib[c]*LINV + bos[c];
          if (nb == 0) out[(((size_t)b*NCn + c)*64 + tt)*128 + (s-1)] = v;
          if (v > best){ best = v; bidx = c-1; }
        }
        cu0 = (lg0 > 0.f) ? 1.f : 0.f;
        cu1 = (float)bidx * (1.f/(VBn-1));
      }
      curbuf[tid*2] = cu0; curbuf[tid*2+1] = cu1;
    }
    __syncthreads();
    gemm_phase<0>(smem, sb, sbuf, nb, m0, tid, lane, wid, curbuf, wo_s, s);
    gridbar(++bar);
    // zero the OTHER parity intbuf (read by L0 this step, rewritten at s+1)
    if (tid < 132) d_intbuf[sbuf ^ 1][cta*132 + tid] = 0;
    gemm_phase<1>(smem, sb, sbuf, nb, m0, tid, lane, wid, curbuf, wo_s, s);
    gridbar(++bar);
  }
  // final out for s = 127
  if (nb == 0 && tid < 128){
    int r = m0 + tid;
    const int* ib = &d_intbuf[1][r*NCn];   // 127 & 1 == 1
    int b = r>>6, tt = r&63;
    #pragma unroll
    for (int c=0;c<NCn;c++)
      out[(((size_t)b*NCn + c)*64 + tt)*128 + 127] = (float)ib[c]*LINV + bos[c];
  }
}

// ============================ launch ============================
extern "C" void kernel_launch(void* const* d_in, const int* in_sizes, int n_in,
                              void* d_out, int out_size){
  const float* x    = (const float*)d_in[0];
  const float* sos  = (const float*)d_in[1];
  const float* Wc   = (const float*)d_in[2];
  const float* bc   = (const float*)d_in[3];
  const float* Wi   = (const float*)d_in[4];
  const float* bi   = (const float*)d_in[5];
  const float* Wih0 = (const float*)d_in[6];
  const float* Whh0 = (const float*)d_in[7];
  const float* bih0 = (const float*)d_in[8];
  const float* bhh0 = (const float*)d_in[9];
  const float* Wih1 = (const float*)d_in[10];
  const float* Whh1 = (const float*)d_in[11];
  const float* bih1 = (const float*)d_in[12];
  const float* bhh1 = (const float*)d_in[13];
  const float* Wo   = (const float*)d_in[14];
  const float* bo   = (const float*)d_in[15];
  float* out = (float*)d_out;

  cudaFuncSetAttribute(k_steps, cudaFuncAttributeMaxDynamicSharedMemorySize, GEMM_SMEM);

  k_init<<<(BTn*Hn+255)/256, 256>>>(sos);
  k_wconv<<<dim3(Gn/64, Hn/64, 3), dim3(64,8)>>>(Whh0, Wih1, Whh1);
  k_prep<<<Gn/128, 128>>>(Wih0, bi, Wi, bih0, bhh0, bih1, bhh1);
  gemm128<0><<<dim3(Hn/128, BTn/128), 256>>>(x, Wc, bc, Hn, En);
  gemm128<1><<<dim3(Gn/128, BTn/128), 256>>>(nullptr, Wih0 + (size_t)Hn*Gn, nullptr, Gn, Hn);

  k_steps<<<NCTA, 256, GEMM_SMEM>>>(Wo, bo, out);
}

// round 9
// speedup vs baseline: 5.9981x; 1.0760x over previous
#include <cuda_runtime.h>
#include <cuda_fp16.h>
#include <math.h>
#include <stdint.h>

#define BTn 512
#define En  512
#define Hn  1024
#define Gn  4096
#define NCn 33
#define VBn 32
#define NSTEPS 128
#define KC 128
#define NCTA 128
#define NTHR 512
#define LSCALE 4194304.0f
#define LINV   2.384185791015625e-07f

// ============================ device globals ============================
__device__ __align__(256) float d_cond[BTn*Hn];
__device__ __align__(256) float d_condG0p[BTn*Gn];   // quad layout: [r][jh*4 + gate]
__device__ __align__(256) float d_bvecM[3*Gn];        // quad: bvec | M2row0 | M2row1
__device__ __align__(256) float d_b1p[Gn];            // quad bih1+bhh1
// weights: [pcol2][k] fp16, pcol2 = ((gate>>1)<<11) | (jh<<1) | (gate&1)
__device__ __align__(256) __half d_Whh0h[Gn*Hn];
__device__ __align__(256) __half d_Wih1h[Gn*Hn];
__device__ __align__(256) __half d_Whh1h[Gn*Hn];
__device__ __align__(256) __half d_h0h[2][BTn*Hn];    // [step parity]
__device__ __align__(256) __half d_h1h[2][BTn*Hn];
__device__ __align__(256) float d_c0[BTn*Hn];
__device__ __align__(256) float d_c1[BTn*Hn];
__device__ __align__(256) float d_cur[BTn*2];
__device__ __align__(256) int d_intbuf[2][BTn*NCn];   // fixed-point logit partial sums
__device__ unsigned d_cnt;
__device__ unsigned d_flag;

__device__ __forceinline__ float sigf(float x){ return 1.f/(1.f+__expf(-x)); }

__device__ __forceinline__ uint32_t smem_u32(const void* p){
  uint32_t a; asm("{ .reg .u64 t; cvta.to.shared.u64 t, %1; cvt.u32.u64 %0, t; }" : "=r"(a) : "l"(p));
  return a;
}

#define MMA16816(d, a, b) \
  asm volatile("mma.sync.aligned.m16n8k16.row.col.f32.f16.f16.f32 " \
    "{%0,%1,%2,%3}, {%4,%5,%6,%7}, {%8,%9}, {%0,%1,%2,%3};" \
    : "+f"((d)[0]), "+f"((d)[1]), "+f"((d)[2]), "+f"((d)[3]) \
    : "r"((a)[0]), "r"((a)[1]), "r"((a)[2]), "r"((a)[3]), "r"((b)[0]), "r"((b)[1]))

// ---- grid barrier ----
__device__ __forceinline__ void gridbar(unsigned target){
  __syncthreads();
  if (threadIdx.x == 0){
    __threadfence();
    unsigned old = atomicAdd(&d_cnt, 1u);
    if (old == target*NCTA - 1u){
      asm volatile("st.release.gpu.u32 [%0], %1;" :: "l"(&d_flag), "r"(target) : "memory");
    } else {
      unsigned v;
      do { asm volatile("ld.acquire.gpu.u32 %0, [%1];" : "=r"(v) : "l"(&d_flag) : "memory"); }
      while (v < target);
    }
  }
  __syncthreads();
}

// ============================ init ============================
__global__ void k_init(const float* __restrict__ sos){
  int idx = blockIdx.x*blockDim.x + threadIdx.x;
  if (idx < BTn*Hn){
    d_c0[idx]=0.f; d_c1[idx]=0.f;
    __half z = __float2half(0.f);
    d_h0h[0][idx]=z; d_h0h[1][idx]=z; d_h1h[0][idx]=z; d_h1h[1][idx]=z;
  }
  if (idx < BTn){ d_cur[idx*2+0]=sos[0]; d_cur[idx*2+1]=sos[1]; }
  if (idx < 2*BTn*NCn) ((int*)d_intbuf)[idx] = 0;
  if (idx == 0){ d_cnt = 0u; d_flag = 0u; }
}

// ============ weight convert: transpose + pcol2 permute + fp16 ============
__global__ void k_wconv(const float* __restrict__ W0, const float* __restrict__ W1,
                        const float* __restrict__ W2){
  __shared__ float ts[64][65];
  const float* W = (blockIdx.z==0)? W0 : (blockIdx.z==1)? W1 : W2;
  __half* Dhi = (blockIdx.z==0)? d_Whh0h : (blockIdx.z==1)? d_Wih1h : d_Whh1h;
  int c0 = blockIdx.x*64, k0 = blockIdx.y*64;
  int tx = threadIdx.x, ty = threadIdx.y;
  #pragma unroll
  for (int i=0;i<8;i++){
    int kl = ty + i*8;
    ts[kl][tx] = W[(size_t)(k0+kl)*Gn + c0 + tx];
  }
  __syncthreads();
  #pragma unroll
  for (int i=0;i<8;i++){
    int lc = ty + i*8;
    int c = c0 + lc;
    int q = c >> 10, jh = c & 1023;
    int pcol = ((q>>1)<<11) | (jh<<1) | (q&1);
    Dhi[(size_t)pcol*Hn + k0 + tx] = __float2half_rn(ts[tx][lc]);
  }
}

// ======== bvec/M2/b1 precompute (quad layout: jh*4+gate) ========
__global__ void k_prep(const float* __restrict__ Wih0, const float* __restrict__ bi,
                       const float* __restrict__ Wi,   const float* __restrict__ bih0,
                       const float* __restrict__ bhh0, const float* __restrict__ bih1,
                       const float* __restrict__ bhh1){
  int j = blockIdx.x*blockDim.x + threadIdx.x;
  float ab=0.f, a0=0.f, a1=0.f;
  for (int k=0;k<Hn;k++){
    float w = Wih0[(size_t)k*Gn + j];
    ab = fmaf(bi[k],    w, ab);
    a0 = fmaf(Wi[k],    w, a0);
    a1 = fmaf(Wi[Hn+k], w, a1);
  }
  int pcol = ((j & 1023) << 2) | (j >> 10);
  d_bvecM[pcol]        = bih0[j] + bhh0[j] + ab;
  d_bvecM[Gn+pcol]     = a0;
  d_bvecM[2*Gn+pcol]   = a1;
  d_b1p[pcol]          = bih1[j] + bhh1[j];
}

// ============ one-time fp32 GEMM (cond and condG0p) ============
#define AS_LD 132
template<int MODE>
__global__ __launch_bounds__(256) void gemm128(const float* __restrict__ Aext,
    const float* __restrict__ W, const float* __restrict__ biasExt, int N, int K)
{
  __shared__ float As[16*AS_LD];
  __shared__ float Ws[16*AS_LD];
  const int m0 = blockIdx.y*128, n0 = blockIdx.x*128;
  const int tid = threadIdx.x;
  const int trow = tid>>4, tcol = tid&15;
  float acc[8][8];
  #pragma unroll
  for(int i=0;i<8;i++){
    #pragma unroll
    for(int j=0;j<8;j++) acc[i][j]=0.f;
  }
  const float* Ap = MODE ? d_cond : Aext;
  for (int k0=0;k0<K;k0+=16){
    #pragma unroll
    for (int i=0;i<2;i++){
      int f = tid + i*256;
      int r = f>>2, c = f&3;
      float4 v = *(const float4*)(Ap + (size_t)(m0+r)*K + k0 + c*4);
      As[(c*4+0)*AS_LD + r]=v.x; As[(c*4+1)*AS_LD + r]=v.y;
      As[(c*4+2)*AS_LD + r]=v.z; As[(c*4+3)*AS_LD + r]=v.w;
    }
    #pragma unroll
    for (int i=0;i<2;i++){
      int f = tid + i*256;
      int kr = f>>5, nc = f&31;
      *(float4*)(&Ws[kr*AS_LD + nc*4]) = *(const float4*)(W + (size_t)(k0+kr)*N + n0 + nc*4);
    }
    __syncthreads();
    #pragma unroll
    for (int kk=0;kk<16;kk++){
      float a[8], b[8];
      *(float4*)(a)   = *(const float4*)(&As[kk*AS_LD + trow*8]);
      *(float4*)(a+4) = *(const float4*)(&As[kk*AS_LD + trow*8+4]);
      *(float4*)(b)   = *(const float4*)(&Ws[kk*AS_LD + tcol*8]);
      *(float4*)(b+4) = *(const float4*)(&Ws[kk*AS_LD + tcol*8+4]);
      #pragma unroll
      for(int i=0;i<8;i++){
        #pragma unroll
        for(int j=0;j<8;j++) acc[i][j] = fmaf(a[i], b[j], acc[i][j]);
      }
    }
    __syncthreads();
  }
  #pragma unroll
  for (int i=0;i<8;i++){
    int r = m0 + trow*8 + i;
    #pragma unroll
    for (int j=0;j<8;j++){
      int col = n0 + tcol*8 + j;
      float v = acc[i][j];
      if (MODE==0){
        v += biasExt[col];
        d_cond[(size_t)r*N + col] = v;
      } else {
        int pcol = ((col & 1023) << 2) | (col >> 10);
        v += d_bvecM[pcol];
        d_condG0p[(size_t)r*N + pcol] = v;
      }
    }
  }
}

// ============================ persistent step kernel ============================
#define STAGE_BYTES 65536
#define NSTAGE 3
#define SM_CUR (NSTAGE*STAGE_BYTES)
#define SM_WO  (SM_CUR + 1024)
#define SM_BO  (SM_WO + 4352)
#define GEMM_SMEM (SM_BO + 256)

__device__ __forceinline__ void load_stage(uint32_t sbase, const __half* Asrc,
    const __half* Whi, int m0, int nb, int k0, int tid){
  #pragma unroll
  for (int it=0; it<8; it++){
    int idx = it*NTHR + tid;       // 0..4095 (16B units)
    int tile = idx >> 11;          // 0:A 1:W
    int rem  = idx & 2047;
    int row  = rem >> 4;           // 0..127
    int cc   = rem & 15;           // 16B chunk within 256B row
    const __half* src;
    if (tile==0) src = Asrc + (size_t)(m0+row)*Hn;
    else {
      int pr = nb*64 + row + ((row>=64)? (2048-64) : 0);
      src = Whi + (size_t)pr*Hn;
    }
    uint32_t daddr = sbase + tile*32768 + row*256 + ((cc ^ (row&7))<<4);
    const void* g = (const void*)(src + k0 + cc*8);
    asm volatile("cp.async.cg.shared.global [%0], [%1], 16;" :: "r"(daddr), "l"(g));
  }
}

// 16 warps: warp tile 32 rows x 32 cols. acc[2][4][4]
__device__ __forceinline__ void compute_stage(uint32_t sbase, float acc[2][4][4],
                                              int lane, int wm, int wn){
  const uint32_t As = sbase, Bh = sbase + 32768;
  #pragma unroll
  for (int kk=0; kk<8; kk++){
    uint32_t a[2][4];
    #pragma unroll
    for (int mt=0; mt<2; mt++){
      int m = wm*32 + mt*16 + (lane & 15);
      int ch = kk*2 + (lane>>4);
      uint32_t addr = As + m*256 + ((ch ^ (m&7))<<4);
      asm volatile("ldmatrix.sync.aligned.m8n8.x4.shared.b16 {%0,%1,%2,%3}, [%4];"
        : "=r"(a[mt][0]),"=r"(a[mt][1]),"=r"(a[mt][2]),"=r"(a[mt][3]) : "r"(addr));
    }
    // B: two x4 loads, each covering an nt-pair x both k-halves
    uint32_t bh[4][2];
    #pragma unroll
    for (int np=0; np<2; np++){
      int mat = lane >> 3;
      int ntl = np*2 + (mat>>1);
      int ch  = kk*2 + (mat&1);
      int rb = (ntl<2 ? wn*16 + ntl*8 : 64 + wn*16 + (ntl-2)*8) + (lane&7);
      uint32_t addr = Bh + rb*256 + ((ch ^ (rb&7))<<4);
      uint32_t r0,r1,r2,r3;
      asm volatile("ldmatrix.sync.aligned.m8n8.x4.shared.b16 {%0,%1,%2,%3}, [%4];"
        : "=r"(r0),"=r"(r1),"=r"(r2),"=r"(r3) : "r"(addr));
      bh[np*2+0][0]=r0; bh[np*2+0][1]=r1;
      bh[np*2+1][0]=r2; bh[np*2+1][1]=r3;
    }
    #pragma unroll
    for (int mt=0; mt<2; mt++){
      #pragma unroll
      for (int nt=0; nt<4; nt++){
        MMA16816(acc[mt][nt], a[mt], bh[nt]);
      }
    }
  }
}

template<int LAYER>
__device__ __forceinline__ void chunk_src(int sbuf, int ch, const __half*& A,
    const __half*& Wh, int& k0){
  if (LAYER==0){ A = d_h0h[sbuf^1]; Wh = d_Whh0h; k0 = ch*KC; }
  else if (ch < 8){ A = d_h0h[sbuf]; Wh = d_Wih1h; k0 = ch*KC; }
  else { A = d_h1h[sbuf^1]; Wh = d_Whh1h; k0 = (ch-8)*KC; }
}

template<int LAYER>
__device__ __forceinline__ void gemm_phase(char* smem, uint32_t sb, int sbuf, int nb, int m0,
    int tid, int lane, int wid, const float* curbuf, const float* wo_s, int s){
  const int wm = wid >> 2, wn = wid & 3;
  const int nch = LAYER ? 16 : 8;

  float acc[2][4][4];
  #pragma unroll
  for (int i=0;i<2;i++){
    #pragma unroll
    for (int j=0;j<4;j++){
      #pragma unroll
      for (int k=0;k<4;k++) acc[i][j][k]=0.f;
    }
  }

  #pragma unroll
  for (int p=0;p<2;p++){
    const __half *A, *Wh; int k0;
    chunk_src<LAYER>(sbuf, p, A, Wh, k0);
    load_stage(sb + p*STAGE_BYTES, A, Wh, m0, nb, k0, tid);
    asm volatile("cp.async.commit_group;");
  }
  for (int ch=0; ch<nch; ch++){
    asm volatile("cp.async.wait_group 1;");
    __syncthreads();
    if (ch+2 < nch){
      const __half *A, *Wh; int k0;
      chunk_src<LAYER>(sbuf, ch+2, A, Wh, k0);
      load_stage(sb + ((ch+2)%NSTAGE)*STAGE_BYTES, A, Wh, m0, nb, k0, tid);
    }
    asm volatile("cp.async.commit_group;");
    compute_stage(sb + (ch%NSTAGE)*STAGE_BYTES, acc, lane, wm, wn);
  }
  asm volatile("cp.async.wait_group 0;");
  __syncthreads();

  // ---- fused LSTM cell epilogue (warp: 32 rows x 32 cols) ----
  const int q  = lane & 3;
  const int tq = lane >> 2;
  float* cst = LAYER ? d_c1 : d_c0;
  __half* hout = LAYER ? d_h1h[sbuf] : d_h0h[sbuf];
  float* hbuf = (float*)smem;    // stage0 region reuse (L1 only)

  #pragma unroll
  for (int mt=0; mt<2; mt++){
    #pragma unroll
    for (int rr=0; rr<2; rr++){
      int lr = wm*32 + mt*16 + tq + rr*8;
      int r = m0 + lr;
      float cu0 = 0.f, cu1 = 0.f;
      if (LAYER == 0){ cu0 = curbuf[2*lr]; cu1 = curbuf[2*lr+1]; }
      #pragma unroll
      for (int nt=0; nt<2; nt++){
        int cloc = wn*8 + nt*4 + q;
        int jh = nb*32 + cloc;
        float vi = acc[mt][nt  ][rr*2+0];
        float vf = acc[mt][nt  ][rr*2+1];
        float vg = acc[mt][nt+2][rr*2+0];
        float vo = acc[mt][nt+2][rr*2+1];
        if (LAYER == 0){
          float4 pg = *(const float4*)&d_condG0p[(size_t)r*Gn + jh*4];
          float4 ma = *(const float4*)&d_bvecM[Gn + jh*4];
          float4 mb = *(const float4*)&d_bvecM[2*Gn + jh*4];
          vi += pg.x + cu0*ma.x + cu1*mb.x;
          vf += pg.y + cu0*ma.y + cu1*mb.y;
          vg += pg.z + cu0*ma.z + cu1*mb.z;
          vo += pg.w + cu0*ma.w + cu1*mb.w;
        } else {
          float4 b1 = *(const float4*)&d_b1p[jh*4];
          vi += b1.x; vf += b1.y; vg += b1.z; vo += b1.w;
        }
        size_t off = (size_t)r*Hn + jh;
        float co = cst[off];
        float cn = sigf(vf)*co + sigf(vi)*tanhf(vg);
        cst[off] = cn;
        float h = sigf(vo)*tanhf(cn);
        hout[off] = __float2half_rn(h);
        if (LAYER) hbuf[lr*33 + cloc] = h;
      }
    }
  }

  // ---- L1: partial logits over this CTA's 32 columns, int atomics ----
  if (LAYER == 1){
    __syncthreads();
    const int lr = tid >> 2, qt = tid & 3;   // 4 threads per row
    float pacc[NCn];
    #pragma unroll
    for (int c=0;c<NCn;c++) pacc[c]=0.f;
    const float* hb = hbuf + lr*33;
    #pragma unroll
    for (int cc2=0; cc2<8; cc2++){
      int col = qt*8 + cc2;
      float h = hb[col];
      const float* wr = wo_s + col*34;
      #pragma unroll
      for (int o=0;o<NCn;o++) pacc[o] = fmaf(h, wr[o], pacc[o]);
    }
    int* ob = &d_intbuf[sbuf][(m0+lr)*NCn];
    #pragma unroll
    for (int o=0;o<NCn;o++){
      float v = pacc[o];
      v += __shfl_xor_sync(0xffffffffu, v, 1);
      v += __shfl_xor_sync(0xffffffffu, v, 2);
      if (qt == 0) atomicAdd(&ob[o], __float2int_rn(v*LSCALE));
    }
  }
}

__global__ __launch_bounds__(NTHR, 1) void k_steps(const float* __restrict__ Wo,
    const float* __restrict__ bo, float* __restrict__ out){
  extern __shared__ char smem[];
  const uint32_t sb = smem_u32(smem);
  float* curbuf = (float*)(smem + SM_CUR);
  float* wo_s   = (float*)(smem + SM_WO);
  float* bos    = (float*)(smem + SM_BO);
  const int tid = threadIdx.x;
  const int lane = tid & 31, wid = tid >> 5;
  const int cta = blockIdx.x;
  const int nb = cta & 31, m0 = (cta >> 5) * 128;

  for (int i=tid; i<32*NCn; i+=NTHR){
    int col = i/NCn, c = i - col*NCn;
    wo_s[col*34+c] = Wo[(size_t)(nb*32+col)*NCn + c];
  }
  if (tid < NCn) bos[tid] = bo[tid];
  __syncthreads();

  unsigned bar = 0;
  for (int s=0; s<NSTEPS; s++){
    const int sbuf = s & 1;
    if (tid < 128){
      int r = m0 + tid;
      float cu0, cu1;
      if (s == 0){
        cu0 = d_cur[2*r]; cu1 = d_cur[2*r+1];
      } else {
        const int* ib = &d_intbuf[(s-1)&1][r*NCn];
        int b = r>>6, tt = r&63;
        float lg0 = (float)ib[0]*LINV + bos[0];
        if (nb == 0) out[(((size_t)b*NCn + 0)*64 + tt)*128 + (s-1)] = lg0;
        float best = -3.4e38f; int bidx = 0;
        #pragma unroll
        for (int c=1;c<NCn;c++){
          float v = (float)ib[c]*LINV + bos[c];
          if (nb == 0) out[(((size_t)b*NCn + c)*64 + tt)*128 + (s-1)] = v;
          if (v > best){ best = v; bidx = c-1; }
        }
        cu0 = (lg0 > 0.f) ? 1.f : 0.f;
        cu1 = (float)bidx * (1.f/(VBn-1));
      }
      curbuf[tid*2] = cu0; curbuf[tid*2+1] = cu1;
    }
    __syncthreads();
    gemm_phase<0>(smem, sb, sbuf, nb, m0, tid, lane, wid, curbuf, wo_s, s);
    gridbar(++bar);
    if (tid < 132) d_intbuf[sbuf ^ 1][cta*132 + tid] = 0;
    gemm_phase<1>(smem, sb, sbuf, nb, m0, tid, lane, wid, curbuf, wo_s, s);
    gridbar(++bar);
  }
  if (nb == 0 && tid < 128){
    int r = m0 + tid;
    const int* ib = &d_intbuf[1][r*NCn];
    int b = r>>6, tt = r&63;
    #pragma unroll
    for (int c=0;c<NCn;c++)
      out[(((size_t)b*NCn + c)*64 + tt)*128 + 127] = (float)ib[c]*LINV + bos[c];
  }
}

// ============================ launch ============================
extern "C" void kernel_launch(void* const* d_in, const int* in_sizes, int n_in,
                              void* d_out, int out_size){
  const float* x    = (const float*)d_in[0];
  const float* sos  = (const float*)d_in[1];
  const float* Wc   = (const float*)d_in[2];
  const float* bc   = (const float*)d_in[3];
  const float* Wi   = (const float*)d_in[4];
  const float* bi   = (const float*)d_in[5];
  const float* Wih0 = (const float*)d_in[6];
  const float* Whh0 = (const float*)d_in[7];
  const float* bih0 = (const float*)d_in[8];
  const float* bhh0 = (const float*)d_in[9];
  const float* Wih1 = (const float*)d_in[10];
  const float* Whh1 = (const float*)d_in[11];
  const float* bih1 = (const float*)d_in[12];
  const float* bhh1 = (const float*)d_in[13];
  const float* Wo   = (const float*)d_in[14];
  const float* bo   = (const float*)d_in[15];
  float* out = (float*)d_out;

  cudaFuncSetAttribute(k_steps, cudaFuncAttributeMaxDynamicSharedMemorySize, GEMM_SMEM);

  k_init<<<(BTn*Hn+255)/256, 256>>>(sos);
  k_wconv<<<dim3(Gn/64, Hn/64, 3), dim3(64,8)>>>(Whh0, Wih1, Whh1);
  k_prep<<<Gn/128, 128>>>(Wih0, bi, Wi, bih0, bhh0, bih1, bhh1);
  gemm128<0><<<dim3(Hn/128, BTn/128), 256>>>(x, Wc, bc, Hn, En);
  gemm128<1><<<dim3(Gn/128, BTn/128), 256>>>(nullptr, Wih0 + (size_t)Hn*Gn, nullptr, Gn, Hn);

  k_steps<<<NCTA, NTHR, GEMM_SMEM>>>(Wo, bo, out);
}